// round 11
// baseline (speedup 1.0000x reference)
#include <cuda_runtime.h>
#include <cuda_fp16.h>
#include <cstdint>

// Problem constants
#define Hn 128
#define Vn 256
#define BV 1024            // B*V node count
#define NE 262144          // B*V*V edge count

// ------------------------- device scratch --------------------------------
__device__ float g_Uh[BV * Hn];
__device__ float g_Vh[BV * Hn];
__device__ float g_Ah[BV * Hn];
__device__ float g_Bh[BV * Hn];
__device__ float g_hpre[BV * Hn];
__device__ float g_hpp[2048 * Hn];     // per-(i,jh) masked-aggregation partial
__device__ float g_ps[2048 * Hn];      // per-(i,jh) per-channel sum of e_new
__device__ float g_ps2[2048 * Hn];
__device__ float g_pd0[NE];            // pa-dot partial, n-half 0
__device__ float g_pd1[NE];            // pa-dot partial, n-half 1
__device__ float g_pse[256 * Hn], g_pse2[256 * Hn];   // stats partials
__device__ float g_psh[256 * Hn], g_psh2[256 * Hn];
__device__ float g_rs_e[Hn], g_ofs_e[Hn];
__device__ float g_rs_h[Hn], g_ofs_h[Hn];
__device__ uint8_t g_CwHi[32768];      // pre-swizzled fp16 Cw
__device__ __half g_enew[(size_t)NE * Hn];   // e_new in fp16 (64 MB)
__device__ unsigned int g_cnt = 0;     // stats completion counter

__device__ __forceinline__ float sigmoidf_(float v) {
    return 1.0f / (1.0f + __expf(-v));
}

__device__ __forceinline__ uint32_t smem_u32(const void* p) {
    uint32_t a;
    asm("{ .reg .u64 t; cvta.to.shared.u64 t, %1; cvt.u32.u64 %0, t; }"
        : "=r"(a) : "l"(p));
    return a;
}

__device__ __forceinline__ uint32_t h2u(__half2 h) {
    return *reinterpret_cast<uint32_t*>(&h);
}

__device__ __forceinline__ __half2 u2h(uint32_t u) {
    return *reinterpret_cast<__half2*>(&u);
}

__device__ __forceinline__ void ldsm_x4(uint32_t& r0, uint32_t& r1, uint32_t& r2,
                                        uint32_t& r3, uint32_t addr) {
    asm volatile("ldmatrix.sync.aligned.m8n8.x4.shared.b16 {%0,%1,%2,%3}, [%4];"
                 : "=r"(r0), "=r"(r1), "=r"(r2), "=r"(r3) : "r"(addr));
}

__device__ __forceinline__ void mma16816(float* d, const uint32_t* a, const uint32_t* b) {
    asm volatile(
        "mma.sync.aligned.m16n8k16.row.col.f32.f16.f16.f32 "
        "{%0,%1,%2,%3}, {%4,%5,%6,%7}, {%8,%9}, {%0,%1,%2,%3};"
        : "+f"(d[0]), "+f"(d[1]), "+f"(d[2]), "+f"(d[3])
        : "r"(a[0]), "r"(a[1]), "r"(a[2]), "r"(a[3]), "r"(b[0]), "r"(b[1]));
}

__device__ __forceinline__ int sw_off(int idx /*float4 index*/) {
    int row = idx >> 5;
    int c4f = idx & 31;
    return row * 256 + (((c4f >> 1) ^ (row & 7)) << 4) + ((c4f & 1) << 3);
}

// ------------------------- K0: fused Cw prep + node linears ---------------
// grid 80: blocks 0..15 convert Cw, blocks 16..79 do node linears
__global__ void k_pre(const float* __restrict__ h, const float* __restrict__ Cw,
                      const float* __restrict__ Uw, const float* __restrict__ Ub,
                      const float* __restrict__ Vw, const float* __restrict__ Vb,
                      const float* __restrict__ Aw, const float* __restrict__ Ab,
                      const float* __restrict__ Bw, const float* __restrict__ Bb) {
    __shared__ float hs[16 * Hn];
    int tid = threadIdx.x;
    int bx = blockIdx.x;
    if (bx < 16) {
        int idx = bx * 256 + tid;     // 4096 float4s
        float4 v = __ldg((const float4*)Cw + idx);
        __half2 h0 = __floats2half2_rn(v.x, v.y);
        __half2 h1 = __floats2half2_rn(v.z, v.w);
        *(uint2*)(g_CwHi + sw_off(idx)) = make_uint2(h2u(h0), h2u(h1));
        return;
    }
    int row0 = (bx - 16) * 16;
    for (int idx = tid; idx < 16 * Hn; idx += 256)
        hs[idx] = h[(size_t)row0 * Hn + idx];
    __syncthreads();
    const float* Ws[4] = {Uw, Vw, Aw, Bw};
    const float* bs[4] = {Ub, Vb, Ab, Bb};
    float* outs[4];
    outs[0] = g_Uh; outs[1] = g_Vh; outs[2] = g_Ah; outs[3] = g_Bh;
    for (int p = 0; p < 2; p++) {
        int cid = tid + 256 * p;
        int m = cid >> 7;
        int o = cid & 127;
        const float* W = Ws[m] + (size_t)o * Hn;
        float acc[16];
        #pragma unroll
        for (int r = 0; r < 16; r++) acc[r] = 0.f;
        for (int k = 0; k < Hn; k += 4) {
            float4 w = *(const float4*)(W + k);
            #pragma unroll
            for (int r = 0; r < 16; r++) {
                acc[r] += hs[r * Hn + k] * w.x + hs[r * Hn + k + 1] * w.y +
                          hs[r * Hn + k + 2] * w.z + hs[r * Hn + k + 3] * w.w;
            }
        }
        float bias = bs[m][o];
        float* op = outs[m] + (size_t)row0 * Hn + o;
        #pragma unroll
        for (int r = 0; r < 16; r++) op[(size_t)r * Hn] = acc[r] + bias;
    }
}

// ------------------------- K1: main kernel (128j x 64n tile, fp16) --------
// grid 4096: blockIdx = ((i_glob*2 + jh)*2 + nh)
static constexpr int SA      = 0;      // 32768
static constexpr int SB      = 32768;  // 16384 -> 49152
// post-MMA aliases:
static constexpr int SM_STG  = 0;      // 128 x 32 uint32 (fp16 stage) = 16384
static constexpr int SM_PD   = 16384;  // 128 x 17 f = 8704 (inside SA)
static constexpr int SM_RPS  = 32768;  // 16x64 f -> 36864
static constexpr int SM_RPS2 = 36864;  // -> 40960
static constexpr int SM_RM   = 40960;  // -> 45056 (inside SB)
// persistent misc:
static constexpr int SM_BC   = 49152;  // 128 f
static constexpr int SM_DW   = 49664;
static constexpr int SM_EW   = 50176;
static constexpr int SM_DIST = 50688;
static constexpr int SM_GR   = 51200;  // -> 51712
static constexpr int SMEM_MAIN = 51712;

__global__ void __launch_bounds__(256, 4)
k_main(const float* __restrict__ e, const float* __restrict__ x,
       const int* __restrict__ graph, const float* __restrict__ Cb,
       const float* __restrict__ dwv, const float* __restrict__ dbv,
       const float* __restrict__ ewv) {
    extern __shared__ char sm[];
    uint32_t smb = smem_u32(sm);
    int tid = threadIdx.x;
    int wid = tid >> 5;
    int lane = tid & 31;

    int bx = blockIdx.x;
    int i_glob = bx >> 2;          // b*V + i
    int jh = (bx >> 1) & 1;
    int nh = bx & 1;
    int b = i_glob >> 8;
    int jbase = jh * 128;

    float* sBC   = (float*)(sm + SM_BC);
    float* sdw   = (float*)(sm + SM_DW);
    float* sew   = (float*)(sm + SM_EW);
    float* sdist = (float*)(sm + SM_DIST);
    int*   sgr   = (int*)(sm + SM_GR);
    float* spd   = (float*)(sm + SM_PD);
    float* rps   = (float*)(sm + SM_RPS);
    float* rps2  = (float*)(sm + SM_RPS2);
    float* rmm   = (float*)(sm + SM_RM);

    float xi = x[i_glob * 2], yi = x[i_glob * 2 + 1];
    if (tid < 128) {
        sBC[tid] = g_Bh[(size_t)i_glob * Hn + tid] + Cb[tid] + dbv[tid];
        sdw[tid] = dwv[tid];
        sew[tid] = ewv[tid];
        int jg = jbase + tid;
        float dx = xi - x[(b * Vn + jg) * 2];
        float dy = yi - x[(b * Vn + jg) * 2 + 1];
        float d2 = dx * dx + dy * dy;
        sdist[tid] = d2 > 0.f ? sqrtf(d2) : 0.f;
        sgr[tid] = graph[(size_t)i_glob * Vn + jg];
    }

    // A: load + convert e tile (128x128) to fp16
    {
        const float4* src = (const float4*)(e + ((size_t)i_glob * Vn + jbase) * Hn);
        #pragma unroll
        for (int q = 0; q < 16; q++) {
            int idx = tid + 256 * q;
            float4 v = __ldg(src + idx);
            __half2 h0 = __floats2half2_rn(v.x, v.y);
            __half2 h1 = __floats2half2_rn(v.z, v.w);
            *(uint2*)(sm + SA + sw_off(idx)) = make_uint2(h2u(h0), h2u(h1));
        }
    }
    // B: straight copy of pre-converted Cw rows [nh*64, nh*64+64)
    {
        const uint4* srcH = (const uint4*)(g_CwHi) + nh * 1024;
        uint4* dstH = (uint4*)(sm + SB);
        #pragma unroll
        for (int t = tid; t < 1024; t += 256)
            dstH[t] = __ldg(srcH + t);
    }
    __syncthreads();

    // ---- MMA: warp grid 4(m) x 2(n); warp tile 32x32 ----
    int wm = wid & 3;
    int wn = wid >> 2;

    float acc[2][4][4];
    #pragma unroll
    for (int mi = 0; mi < 2; mi++)
        #pragma unroll
        for (int ni = 0; ni < 4; ni++)
            #pragma unroll
            for (int c = 0; c < 4; c++) acc[mi][ni][c] = 0.f;

    int la7 = lane & 7;
    int rowA_base = wm * 32 + la7 + ((lane >> 3) & 1) * 8;
    int a_ch = lane >> 4;
    int b_tile = lane >> 3;
    int b_nip = b_tile >> 1;
    int b_ch = b_tile & 1;
    int rowB_lane = wn * 32 + la7;

    #pragma unroll
    for (int ks = 0; ks < 8; ks++) {
        uint32_t ah[2][4];
        #pragma unroll
        for (int mi = 0; mi < 2; mi++) {
            int r = rowA_base + mi * 16;
            uint32_t off = r * 256 + (((ks * 2 + a_ch) ^ (r & 7)) << 4);
            ldsm_x4(ah[mi][0], ah[mi][1], ah[mi][2], ah[mi][3], smb + SA + off);
        }
        uint32_t bh[4][2];
        #pragma unroll
        for (int p = 0; p < 2; p++) {
            int r = rowB_lane + (p * 2 + b_nip) * 8;
            uint32_t off = r * 256 + (((ks * 2 + b_ch) ^ (r & 7)) << 4);
            ldsm_x4(bh[p * 2][0], bh[p * 2][1], bh[p * 2 + 1][0], bh[p * 2 + 1][1],
                    smb + SB + off);
        }
        #pragma unroll
        for (int mi = 0; mi < 2; mi++)
            #pragma unroll
            for (int ni = 0; ni < 4; ni++)
                mma16816(acc[mi][ni], ah[mi], bh[ni]);
    }
    __syncthreads();   // MMA done: SA -> stage+pd, SB -> reductions

    // ---- stage accumulators as fp16 into SM_STG (128 rows x 32 half2) ----
    uint32_t* stage16 = (uint32_t*)(sm + SM_STG);
    {
        #pragma unroll
        for (int mi = 0; mi < 2; mi++) {
            #pragma unroll
            for (int rh = 0; rh < 2; rh++) {
                int r = wm * 32 + mi * 16 + (lane >> 2) + rh * 8;
                int sx = (r & 7) << 2;
                #pragma unroll
                for (int ni = 0; ni < 4; ni++) {
                    int hc = wn * 16 + ni * 4 + (lane & 3);
                    __half2 hp = __floats2half2_rn(acc[mi][ni][rh * 2],
                                                   acc[mi][ni][rh * 2 + 1]);
                    stage16[r * 32 + (hc ^ sx)] = h2u(hp);
                }
            }
        }
    }
    __syncthreads();

    // ---- coalesced epilogue: thread = (row-group rg, col-group cg4) ----
    int cg4 = tid & 15;
    int rg  = tid >> 4;
    int cgl = cg4 * 4;
    int cgg = nh * 64 + cgl;
    float4 bc4 = *(const float4*)(sBC + cgg);
    float4 dw4 = *(const float4*)(sdw + cgg);
    float4 ew4 = *(const float4*)(sew + cgg);
    float4 cs  = make_float4(0.f, 0.f, 0.f, 0.f);
    float4 cq  = make_float4(0.f, 0.f, 0.f, 0.f);
    float4 cm  = make_float4(0.f, 0.f, 0.f, 0.f);

    __half* eh = g_enew + ((size_t)i_glob * Vn + jbase) * Hn;

    #pragma unroll
    for (int k = 0; k < 8; k++) {
        int r = rg + 16 * k;
        int hc2 = (cg4 * 2) ^ ((r & 7) << 2);
        uint2 sv = *(const uint2*)(stage16 + r * 32 + hc2);
        float2 f01 = __half22float2(u2h(sv.x));
        float2 f23 = __half22float2(u2h(sv.y));
        size_t nrow = ((size_t)(b * Vn + jbase + r)) * Hn + cgg;
        float4 a  = __ldg((const float4*)(g_Ah + nrow));
        float4 vh = __ldg((const float4*)(g_Vh + nrow));
        float dist = sdist[r];
        bool keep = (sgr[r] != 1);
        float t0 = f01.x + a.x + bc4.x + dist * dw4.x;
        float t1 = f01.y + a.y + bc4.y + dist * dw4.y;
        float t2 = f23.x + a.z + bc4.z + dist * dw4.z;
        float t3 = f23.y + a.w + bc4.w + dist * dw4.w;
        __half2 p0 = __floats2half2_rn(t0, t1);
        __half2 p1 = __floats2half2_rn(t2, t3);
        *(uint2*)(eh + (size_t)r * Hn + cgg) = make_uint2(h2u(p0), h2u(p1));
        cs.x += t0; cs.y += t1; cs.z += t2; cs.w += t3;
        cq.x += t0 * t0; cq.y += t1 * t1; cq.z += t2 * t2; cq.w += t3 * t3;
        if (keep) {
            cm.x += sigmoidf_(t0) * vh.x;
            cm.y += sigmoidf_(t1) * vh.y;
            cm.z += sigmoidf_(t2) * vh.z;
            cm.w += sigmoidf_(t3) * vh.w;
        }
        spd[r * 17 + cg4] = t0 * ew4.x + t1 * ew4.y + t2 * ew4.z + t3 * ew4.w;
    }

    *(float4*)(rps  + rg * 64 + cgl) = cs;
    *(float4*)(rps2 + rg * 64 + cgl) = cq;
    *(float4*)(rmm  + rg * 64 + cgl) = cm;
    __syncthreads();

    if (tid < 64) {
        float s = 0.f, s2 = 0.f, mm = 0.f;
        #pragma unroll
        for (int g = 0; g < 16; g++) {
            s  += rps[g * 64 + tid];
            s2 += rps2[g * 64 + tid];
            mm += rmm[g * 64 + tid];
        }
        size_t gi = ((size_t)i_glob * 2 + jh) * Hn + nh * 64 + tid;
        g_ps[gi]  = s;
        g_ps2[gi] = s2;
        g_hpp[gi] = mm;
    }
    if (tid >= 128) {
        int r = tid - 128;
        float pdt = 0.f;
        #pragma unroll
        for (int q = 0; q < 16; q++) pdt += spd[r * 17 + q];
        float* gpd = nh ? g_pd1 : g_pd0;
        gpd[(size_t)i_glob * Vn + jbase + r] = pdt;
    }
}

// ------------------------- K2: fused BN statistics ------------------------
// grid 256 x 128; last block to finish performs the finalize.
__global__ void __launch_bounds__(128)
k_stats(const float* __restrict__ gamma_h, const float* __restrict__ beta_h,
        const float* __restrict__ gamma_e, const float* __restrict__ beta_e) {
    __shared__ bool s_last;
    int ch = threadIdx.x;
    int c = blockIdx.x;        // 256 blocks, 4 nodes each
    double se = 0.0, se2 = 0.0, sh = 0.0, sh2 = 0.0;
    for (int i = c * 4; i < c * 4 + 4; i++) {
        float hv = g_Uh[(size_t)i * Hn + ch] +
                   g_hpp[(size_t)(2 * i) * Hn + ch] +
                   g_hpp[(size_t)(2 * i + 1) * Hn + ch];
        g_hpre[(size_t)i * Hn + ch] = hv;
        sh += (double)hv; sh2 += (double)hv * (double)hv;
        se  += (double)g_ps[(size_t)(2 * i) * Hn + ch]  + (double)g_ps[(size_t)(2 * i + 1) * Hn + ch];
        se2 += (double)g_ps2[(size_t)(2 * i) * Hn + ch] + (double)g_ps2[(size_t)(2 * i + 1) * Hn + ch];
    }
    g_pse[c * Hn + ch]  = (float)se;
    g_pse2[c * Hn + ch] = (float)se2;
    g_psh[c * Hn + ch]  = (float)sh;
    g_psh2[c * Hn + ch] = (float)sh2;

    __threadfence();
    __syncthreads();
    if (ch == 0) {
        unsigned int t = atomicAdd(&g_cnt, 1);
        s_last = (t == 255);
    }
    __syncthreads();
    if (!s_last) return;

    __threadfence();   // acquire all partials
    double te = 0.0, te2 = 0.0, th = 0.0, th2 = 0.0;
    for (int p = 0; p < 256; p++) {
        te  += (double)g_pse[p * Hn + ch];
        te2 += (double)g_pse2[p * Hn + ch];
        th  += (double)g_psh[p * Hn + ch];
        th2 += (double)g_psh2[p * Hn + ch];
    }
    float mu  = (float)(te / (double)NE);
    float var = (float)(te2 / (double)NE) - mu * mu;
    float rs = gamma_e[ch] * rsqrtf(var + 1e-5f);
    g_rs_e[ch] = rs;
    g_ofs_e[ch] = beta_e[ch] - mu * rs;

    float muh  = (float)(th / (double)BV);
    float varh = (float)(th2 / (double)BV) - muh * muh;
    float rsh = gamma_h[ch] * rsqrtf(varh + 1e-5f);
    g_rs_h[ch] = rsh;
    g_ofs_h[ch] = beta_h[ch] - muh * rsh;

    if (ch == 0) g_cnt = 0;   // reset for next graph replay
}

// ------------------------- K3: fused finish (e / h / x) -------------------
__global__ void __launch_bounds__(256)
k_finish(const float* __restrict__ e, float* __restrict__ oe,
         const float* __restrict__ h, float* __restrict__ out_h,
         const float* __restrict__ x, const float* __restrict__ cp,
         const float* __restrict__ ebp, float* __restrict__ out_x) {
    int bx = blockIdx.x;
    if (bx < 8192) {
        int tid = threadIdx.x;
        int base = bx * 1024 + tid;
        int c4 = tid & 31;
        float4 rs = *(const float4*)(g_rs_e + 4 * c4);
        float4 of = *(const float4*)(g_ofs_e + 4 * c4);
        uint2 hv[4];
        float4 ev[4];
        #pragma unroll
        for (int q = 0; q < 4; q++) {
            hv[q] = __ldcs((const uint2*)g_enew + base + q * 256);
            ev[q] = __ldcs((const float4*)e + base + q * 256);
        }
        #pragma unroll
        for (int q = 0; q < 4; q++) {
            float2 e01 = __half22float2(*reinterpret_cast<__half2*>(&hv[q].x));
            float2 e23 = __half22float2(*reinterpret_cast<__half2*>(&hv[q].y));
            float4 r = ev[q];
            r.x += fmaxf(fmaf(e01.x, rs.x, of.x), 0.f);
            r.y += fmaxf(fmaf(e01.y, rs.y, of.y), 0.f);
            r.z += fmaxf(fmaf(e23.x, rs.z, of.z), 0.f);
            r.w += fmaxf(fmaf(e23.y, rs.w, of.w), 0.f);
            __stcs((float4*)oe + base + q * 256, r);
        }
    } else if (bx < 8192 + 512) {
        int idx = (bx - 8192) * 256 + threadIdx.x;
        int ch = idx & 127;
        float v = fmaf(g_hpre[idx], g_rs_h[ch], g_ofs_h[ch]);
        out_h[idx] = h[idx] + fmaxf(v, 0.f);
    } else {
        __shared__ float rx[8], ry[8];
        int i = bx - 8192 - 512;      // node 0..1023
        int j = threadIdx.x;
        int lane = j & 31, wd = j >> 5;
        int b = i >> 8;
        float xi = x[i * 2], yi = x[i * 2 + 1];
        float pd = g_pd0[(size_t)i * Vn + j] + g_pd1[(size_t)i * Vn + j];
        float pa = sigmoidf_(pd + ebp[0]);
        float dx = xi - x[(b * Vn + j) * 2];
        float dy = yi - x[(b * Vn + j) * 2 + 1];
        float px = pa * dx, py = pa * dy;
        #pragma unroll
        for (int o = 16; o > 0; o >>= 1) {
            px += __shfl_xor_sync(0xffffffffu, px, o);
            py += __shfl_xor_sync(0xffffffffu, py, o);
        }
        if (lane == 0) { rx[wd] = px; ry[wd] = py; }
        __syncthreads();
        if (j == 0) {
            float sx = 0.f, sy = 0.f;
            #pragma unroll
            for (int w = 0; w < 8; w++) { sx += rx[w]; sy += ry[w]; }
            float c = cp[0];
            out_x[i * 2]     = xi + c * sx;
            out_x[i * 2 + 1] = yi + c * sy;
        }
    }
}

// ------------------------- launcher ---------------------------------------
extern "C" void kernel_launch(void* const* d_in, const int* in_sizes, int n_in,
                              void* d_out, int out_size) {
    const float* h     = (const float*)d_in[0];
    const float* e     = (const float*)d_in[1];
    const float* x     = (const float*)d_in[2];
    const int*   graph = (const int*)d_in[3];
    const float* Uw = (const float*)d_in[4],  *Ub = (const float*)d_in[5];
    const float* Vw = (const float*)d_in[6],  *Vb = (const float*)d_in[7];
    const float* Aw = (const float*)d_in[8],  *Ab = (const float*)d_in[9];
    const float* Bw = (const float*)d_in[10], *Bb = (const float*)d_in[11];
    const float* Cw = (const float*)d_in[12], *Cb = (const float*)d_in[13];
    const float* dwv = (const float*)d_in[14], *dbv = (const float*)d_in[15];
    const float* ewv = (const float*)d_in[16], *ebp = (const float*)d_in[17];
    const float* cp  = (const float*)d_in[18];
    const float* gh  = (const float*)d_in[19], *bh = (const float*)d_in[20];
    const float* ge  = (const float*)d_in[21], *be = (const float*)d_in[22];

    float* out_h = (float*)d_out;
    float* out_e = out_h + (size_t)BV * Hn;
    float* out_x = out_e + (size_t)NE * Hn;

    cudaFuncSetAttribute(k_main, cudaFuncAttributeMaxDynamicSharedMemorySize, SMEM_MAIN);

    k_pre<<<80, 256>>>(h, Cw, Uw, Ub, Vw, Vb, Aw, Ab, Bw, Bb);
    k_main<<<4096, 256, SMEM_MAIN>>>(e, x, graph, Cb, dwv, dbv, ewv);
    k_stats<<<256, 128>>>(gh, bh, ge, be);
    k_finish<<<8192 + 512 + BV, 256>>>(e, out_e, h, out_h, x, cp, ebp, out_x);
}

// round 12
// speedup vs baseline: 1.4072x; 1.4072x over previous
#include <cuda_runtime.h>
#include <cuda_fp16.h>
#include <cstdint>

// Problem constants
#define Hn 128
#define Vn 256
#define BV 1024            // B*V node count
#define NE 262144          // B*V*V edge count

// ------------------------- device scratch --------------------------------
__device__ float g_Uh[BV * Hn];
__device__ float g_Vh[BV * Hn];
__device__ float g_Ah[BV * Hn];
__device__ float g_Bh[BV * Hn];
__device__ float g_hpre[BV * Hn];
__device__ float g_hpp[2048 * Hn];     // per-(i,jh) masked-aggregation partial
__device__ float g_ps[2048 * Hn];      // per-(i,jh) per-channel sum of e_new
__device__ float g_ps2[2048 * Hn];
__device__ float g_pd0[NE];            // pa-dot partial, n-half 0
__device__ float g_pd1[NE];            // pa-dot partial, n-half 1
__device__ float g_pse[256 * Hn], g_pse2[256 * Hn];   // stats partials
__device__ float g_psh[256 * Hn], g_psh2[256 * Hn];
__device__ float g_rs_e[Hn], g_ofs_e[Hn];
__device__ float g_rs_h[Hn], g_ofs_h[Hn];
__device__ uint8_t g_CwHi[32768];      // pre-swizzled fp16 Cw
__device__ __half g_enew[(size_t)NE * Hn];   // e_new in fp16 (64 MB)

__device__ __forceinline__ float sigmoidf_(float v) {
    return 1.0f / (1.0f + __expf(-v));
}

__device__ __forceinline__ uint32_t smem_u32(const void* p) {
    uint32_t a;
    asm("{ .reg .u64 t; cvta.to.shared.u64 t, %1; cvt.u32.u64 %0, t; }"
        : "=r"(a) : "l"(p));
    return a;
}

__device__ __forceinline__ uint32_t h2u(__half2 h) {
    return *reinterpret_cast<uint32_t*>(&h);
}

__device__ __forceinline__ __half2 u2h(uint32_t u) {
    return *reinterpret_cast<__half2*>(&u);
}

__device__ __forceinline__ void ldsm_x4(uint32_t& r0, uint32_t& r1, uint32_t& r2,
                                        uint32_t& r3, uint32_t addr) {
    asm volatile("ldmatrix.sync.aligned.m8n8.x4.shared.b16 {%0,%1,%2,%3}, [%4];"
                 : "=r"(r0), "=r"(r1), "=r"(r2), "=r"(r3) : "r"(addr));
}

__device__ __forceinline__ void mma16816(float* d, const uint32_t* a, const uint32_t* b) {
    asm volatile(
        "mma.sync.aligned.m16n8k16.row.col.f32.f16.f16.f32 "
        "{%0,%1,%2,%3}, {%4,%5,%6,%7}, {%8,%9}, {%0,%1,%2,%3};"
        : "+f"(d[0]), "+f"(d[1]), "+f"(d[2]), "+f"(d[3])
        : "r"(a[0]), "r"(a[1]), "r"(a[2]), "r"(a[3]), "r"(b[0]), "r"(b[1]));
}

__device__ __forceinline__ int sw_off(int idx /*float4 index*/) {
    int row = idx >> 5;
    int c4f = idx & 31;
    return row * 256 + (((c4f >> 1) ^ (row & 7)) << 4) + ((c4f & 1) << 3);
}

// ------------------------- K0: fused Cw prep + node linears ---------------
// grid 80: blocks 0..15 convert Cw, blocks 16..79 do node linears
__global__ void k_pre(const float* __restrict__ h, const float* __restrict__ Cw,
                      const float* __restrict__ Uw, const float* __restrict__ Ub,
                      const float* __restrict__ Vw, const float* __restrict__ Vb,
                      const float* __restrict__ Aw, const float* __restrict__ Ab,
                      const float* __restrict__ Bw, const float* __restrict__ Bb) {
    __shared__ float hs[16 * Hn];
    int tid = threadIdx.x;
    int bx = blockIdx.x;
    if (bx < 16) {
        int idx = bx * 256 + tid;     // 4096 float4s
        float4 v = __ldg((const float4*)Cw + idx);
        __half2 h0 = __floats2half2_rn(v.x, v.y);
        __half2 h1 = __floats2half2_rn(v.z, v.w);
        *(uint2*)(g_CwHi + sw_off(idx)) = make_uint2(h2u(h0), h2u(h1));
        return;
    }
    int row0 = (bx - 16) * 16;
    for (int idx = tid; idx < 16 * Hn; idx += 256)
        hs[idx] = h[(size_t)row0 * Hn + idx];
    __syncthreads();
    const float* Ws[4] = {Uw, Vw, Aw, Bw};
    const float* bs[4] = {Ub, Vb, Ab, Bb};
    float* outs[4];
    outs[0] = g_Uh; outs[1] = g_Vh; outs[2] = g_Ah; outs[3] = g_Bh;
    for (int p = 0; p < 2; p++) {
        int cid = tid + 256 * p;
        int m = cid >> 7;
        int o = cid & 127;
        const float* W = Ws[m] + (size_t)o * Hn;
        float acc[16];
        #pragma unroll
        for (int r = 0; r < 16; r++) acc[r] = 0.f;
        for (int k = 0; k < Hn; k += 4) {
            float4 w = *(const float4*)(W + k);
            #pragma unroll
            for (int r = 0; r < 16; r++) {
                acc[r] += hs[r * Hn + k] * w.x + hs[r * Hn + k + 1] * w.y +
                          hs[r * Hn + k + 2] * w.z + hs[r * Hn + k + 3] * w.w;
            }
        }
        float bias = bs[m][o];
        float* op = outs[m] + (size_t)row0 * Hn + o;
        #pragma unroll
        for (int r = 0; r < 16; r++) op[(size_t)r * Hn] = acc[r] + bias;
    }
}

// ------------------------- K1: main kernel (128j x 64n tile, fp16) --------
// grid 4096: blockIdx = ((i_glob*2 + jh)*2 + nh)
static constexpr int SA      = 0;      // 32768
static constexpr int SB      = 32768;  // 16384 -> 49152
// post-MMA aliases:
static constexpr int SM_STG  = 0;      // 128 x 32 uint32 (fp16 stage) = 16384
static constexpr int SM_PD   = 16384;  // 128 x 17 f = 8704 (inside SA)
static constexpr int SM_RPS  = 32768;  // 16x64 f -> 36864
static constexpr int SM_RPS2 = 36864;  // -> 40960
static constexpr int SM_RM   = 40960;  // -> 45056 (inside SB)
// persistent misc:
static constexpr int SM_BC   = 49152;  // 128 f
static constexpr int SM_DW   = 49664;
static constexpr int SM_EW   = 50176;
static constexpr int SM_DIST = 50688;
static constexpr int SM_GR   = 51200;  // -> 51712
static constexpr int SMEM_MAIN = 51712;

__global__ void __launch_bounds__(256, 4)
k_main(const float* __restrict__ e, const float* __restrict__ x,
       const int* __restrict__ graph, const float* __restrict__ Cb,
       const float* __restrict__ dwv, const float* __restrict__ dbv,
       const float* __restrict__ ewv) {
    extern __shared__ char sm[];
    uint32_t smb = smem_u32(sm);
    int tid = threadIdx.x;
    int wid = tid >> 5;
    int lane = tid & 31;

    int bx = blockIdx.x;
    int i_glob = bx >> 2;          // b*V + i
    int jh = (bx >> 1) & 1;
    int nh = bx & 1;
    int b = i_glob >> 8;
    int jbase = jh * 128;

    float* sBC   = (float*)(sm + SM_BC);
    float* sdw   = (float*)(sm + SM_DW);
    float* sew   = (float*)(sm + SM_EW);
    float* sdist = (float*)(sm + SM_DIST);
    int*   sgr   = (int*)(sm + SM_GR);
    float* spd   = (float*)(sm + SM_PD);
    float* rps   = (float*)(sm + SM_RPS);
    float* rps2  = (float*)(sm + SM_RPS2);
    float* rmm   = (float*)(sm + SM_RM);

    float xi = x[i_glob * 2], yi = x[i_glob * 2 + 1];
    if (tid < 128) {
        sBC[tid] = g_Bh[(size_t)i_glob * Hn + tid] + Cb[tid] + dbv[tid];
        sdw[tid] = dwv[tid];
        sew[tid] = ewv[tid];
        int jg = jbase + tid;
        float dx = xi - x[(b * Vn + jg) * 2];
        float dy = yi - x[(b * Vn + jg) * 2 + 1];
        float d2 = dx * dx + dy * dy;
        sdist[tid] = d2 > 0.f ? sqrtf(d2) : 0.f;
        sgr[tid] = graph[(size_t)i_glob * Vn + jg];
    }

    // A: load + convert e tile (128x128) to fp16
    {
        const float4* src = (const float4*)(e + ((size_t)i_glob * Vn + jbase) * Hn);
        #pragma unroll
        for (int q = 0; q < 16; q++) {
            int idx = tid + 256 * q;
            float4 v = __ldg(src + idx);
            __half2 h0 = __floats2half2_rn(v.x, v.y);
            __half2 h1 = __floats2half2_rn(v.z, v.w);
            *(uint2*)(sm + SA + sw_off(idx)) = make_uint2(h2u(h0), h2u(h1));
        }
    }
    // B: straight copy of pre-converted Cw rows [nh*64, nh*64+64)
    {
        const uint4* srcH = (const uint4*)(g_CwHi) + nh * 1024;
        uint4* dstH = (uint4*)(sm + SB);
        #pragma unroll
        for (int t = tid; t < 1024; t += 256)
            dstH[t] = __ldg(srcH + t);
    }
    __syncthreads();

    // ---- MMA: warp grid 4(m) x 2(n); warp tile 32x32 ----
    int wm = wid & 3;
    int wn = wid >> 2;

    float acc[2][4][4];
    #pragma unroll
    for (int mi = 0; mi < 2; mi++)
        #pragma unroll
        for (int ni = 0; ni < 4; ni++)
            #pragma unroll
            for (int c = 0; c < 4; c++) acc[mi][ni][c] = 0.f;

    int la7 = lane & 7;
    int rowA_base = wm * 32 + la7 + ((lane >> 3) & 1) * 8;
    int a_ch = lane >> 4;
    int b_tile = lane >> 3;
    int b_nip = b_tile >> 1;
    int b_ch = b_tile & 1;
    int rowB_lane = wn * 32 + la7;

    #pragma unroll
    for (int ks = 0; ks < 8; ks++) {
        uint32_t ah[2][4];
        #pragma unroll
        for (int mi = 0; mi < 2; mi++) {
            int r = rowA_base + mi * 16;
            uint32_t off = r * 256 + (((ks * 2 + a_ch) ^ (r & 7)) << 4);
            ldsm_x4(ah[mi][0], ah[mi][1], ah[mi][2], ah[mi][3], smb + SA + off);
        }
        uint32_t bh[4][2];
        #pragma unroll
        for (int p = 0; p < 2; p++) {
            int r = rowB_lane + (p * 2 + b_nip) * 8;
            uint32_t off = r * 256 + (((ks * 2 + b_ch) ^ (r & 7)) << 4);
            ldsm_x4(bh[p * 2][0], bh[p * 2][1], bh[p * 2 + 1][0], bh[p * 2 + 1][1],
                    smb + SB + off);
        }
        #pragma unroll
        for (int mi = 0; mi < 2; mi++)
            #pragma unroll
            for (int ni = 0; ni < 4; ni++)
                mma16816(acc[mi][ni], ah[mi], bh[ni]);
    }
    __syncthreads();   // MMA done: SA -> stage+pd, SB -> reductions

    // ---- stage accumulators as fp16 into SM_STG (128 rows x 32 half2) ----
    uint32_t* stage16 = (uint32_t*)(sm + SM_STG);
    {
        #pragma unroll
        for (int mi = 0; mi < 2; mi++) {
            #pragma unroll
            for (int rh = 0; rh < 2; rh++) {
                int r = wm * 32 + mi * 16 + (lane >> 2) + rh * 8;
                int sx = (r & 7) << 2;
                #pragma unroll
                for (int ni = 0; ni < 4; ni++) {
                    int hc = wn * 16 + ni * 4 + (lane & 3);
                    __half2 hp = __floats2half2_rn(acc[mi][ni][rh * 2],
                                                   acc[mi][ni][rh * 2 + 1]);
                    stage16[r * 32 + (hc ^ sx)] = h2u(hp);
                }
            }
        }
    }
    __syncthreads();

    // ---- coalesced epilogue: thread = (row-group rg, col-group cg4) ----
    int cg4 = tid & 15;
    int rg  = tid >> 4;
    int cgl = cg4 * 4;
    int cgg = nh * 64 + cgl;
    float4 bc4 = *(const float4*)(sBC + cgg);
    float4 dw4 = *(const float4*)(sdw + cgg);
    float4 ew4 = *(const float4*)(sew + cgg);
    float4 cs  = make_float4(0.f, 0.f, 0.f, 0.f);
    float4 cq  = make_float4(0.f, 0.f, 0.f, 0.f);
    float4 cm  = make_float4(0.f, 0.f, 0.f, 0.f);

    __half* eh = g_enew + ((size_t)i_glob * Vn + jbase) * Hn;

    #pragma unroll
    for (int k = 0; k < 8; k++) {
        int r = rg + 16 * k;
        int hc2 = (cg4 * 2) ^ ((r & 7) << 2);
        uint2 sv = *(const uint2*)(stage16 + r * 32 + hc2);
        float2 f01 = __half22float2(u2h(sv.x));
        float2 f23 = __half22float2(u2h(sv.y));
        size_t nrow = ((size_t)(b * Vn + jbase + r)) * Hn + cgg;
        float4 a  = __ldg((const float4*)(g_Ah + nrow));
        float4 vh = __ldg((const float4*)(g_Vh + nrow));
        float dist = sdist[r];
        bool keep = (sgr[r] != 1);
        float t0 = f01.x + a.x + bc4.x + dist * dw4.x;
        float t1 = f01.y + a.y + bc4.y + dist * dw4.y;
        float t2 = f23.x + a.z + bc4.z + dist * dw4.z;
        float t3 = f23.y + a.w + bc4.w + dist * dw4.w;
        __half2 p0 = __floats2half2_rn(t0, t1);
        __half2 p1 = __floats2half2_rn(t2, t3);
        *(uint2*)(eh + (size_t)r * Hn + cgg) = make_uint2(h2u(p0), h2u(p1));
        cs.x += t0; cs.y += t1; cs.z += t2; cs.w += t3;
        cq.x += t0 * t0; cq.y += t1 * t1; cq.z += t2 * t2; cq.w += t3 * t3;
        if (keep) {
            cm.x += sigmoidf_(t0) * vh.x;
            cm.y += sigmoidf_(t1) * vh.y;
            cm.z += sigmoidf_(t2) * vh.z;
            cm.w += sigmoidf_(t3) * vh.w;
        }
        spd[r * 17 + cg4] = t0 * ew4.x + t1 * ew4.y + t2 * ew4.z + t3 * ew4.w;
    }

    *(float4*)(rps  + rg * 64 + cgl) = cs;
    *(float4*)(rps2 + rg * 64 + cgl) = cq;
    *(float4*)(rmm  + rg * 64 + cgl) = cm;
    __syncthreads();

    if (tid < 64) {
        float s = 0.f, s2 = 0.f, mm = 0.f;
        #pragma unroll
        for (int g = 0; g < 16; g++) {
            s  += rps[g * 64 + tid];
            s2 += rps2[g * 64 + tid];
            mm += rmm[g * 64 + tid];
        }
        size_t gi = ((size_t)i_glob * 2 + jh) * Hn + nh * 64 + tid;
        g_ps[gi]  = s;
        g_ps2[gi] = s2;
        g_hpp[gi] = mm;
    }
    if (tid >= 128) {
        int r = tid - 128;
        float pdt = 0.f;
        #pragma unroll
        for (int q = 0; q < 16; q++) pdt += spd[r * 17 + q];
        float* gpd = nh ? g_pd1 : g_pd0;
        gpd[(size_t)i_glob * Vn + jbase + r] = pdt;
    }
}

// ------------------------- K2a: stats partials ----------------------------
__global__ void __launch_bounds__(128)
k_stats1() {
    int ch = threadIdx.x;
    int c = blockIdx.x;        // 256 blocks, 4 nodes each
    double se = 0.0, se2 = 0.0, sh = 0.0, sh2 = 0.0;
    for (int i = c * 4; i < c * 4 + 4; i++) {
        float hv = g_Uh[(size_t)i * Hn + ch] +
                   g_hpp[(size_t)(2 * i) * Hn + ch] +
                   g_hpp[(size_t)(2 * i + 1) * Hn + ch];
        g_hpre[(size_t)i * Hn + ch] = hv;
        sh += (double)hv; sh2 += (double)hv * (double)hv;
        se  += (double)g_ps[(size_t)(2 * i) * Hn + ch]  + (double)g_ps[(size_t)(2 * i + 1) * Hn + ch];
        se2 += (double)g_ps2[(size_t)(2 * i) * Hn + ch] + (double)g_ps2[(size_t)(2 * i + 1) * Hn + ch];
    }
    g_pse[c * Hn + ch]  = (float)se;
    g_pse2[c * Hn + ch] = (float)se2;
    g_psh[c * Hn + ch]  = (float)sh;
    g_psh2[c * Hn + ch] = (float)sh2;
}

// ------------------------- K2b: stats finalize ----------------------------
__global__ void __launch_bounds__(512)
k_stats2(const float* __restrict__ gamma_h, const float* __restrict__ beta_h,
         const float* __restrict__ gamma_e, const float* __restrict__ beta_e) {
    __shared__ double sd[4][Hn][4];
    int tid = threadIdx.x;
    int ch = tid & 127;
    int part = tid >> 7;       // 0..3, 64 blocks each
    double se = 0.0, se2 = 0.0, sh = 0.0, sh2 = 0.0;
    for (int c = part * 64; c < part * 64 + 64; c++) {
        se  += (double)g_pse[c * Hn + ch];
        se2 += (double)g_pse2[c * Hn + ch];
        sh  += (double)g_psh[c * Hn + ch];
        sh2 += (double)g_psh2[c * Hn + ch];
    }
    sd[part][ch][0] = se; sd[part][ch][1] = se2;
    sd[part][ch][2] = sh; sd[part][ch][3] = sh2;
    __syncthreads();
    if (part == 0) {
        for (int r = 1; r < 4; r++) {
            se += sd[r][ch][0]; se2 += sd[r][ch][1];
            sh += sd[r][ch][2]; sh2 += sd[r][ch][3];
        }
        float mu  = (float)(se / (double)NE);
        float var = (float)(se2 / (double)NE) - mu * mu;
        float rs = gamma_e[ch] * rsqrtf(var + 1e-5f);
        g_rs_e[ch] = rs;
        g_ofs_e[ch] = beta_e[ch] - mu * rs;

        float muh  = (float)(sh / (double)BV);
        float varh = (float)(sh2 / (double)BV) - muh * muh;
        float rsh = gamma_h[ch] * rsqrtf(varh + 1e-5f);
        g_rs_h[ch] = rsh;
        g_ofs_h[ch] = beta_h[ch] - muh * rsh;
    }
}

// ------------------------- K3: fused finish (e / h / x) -------------------
__global__ void __launch_bounds__(256)
k_finish(const float* __restrict__ e, float* __restrict__ oe,
         const float* __restrict__ h, float* __restrict__ out_h,
         const float* __restrict__ x, const float* __restrict__ cp,
         const float* __restrict__ ebp, float* __restrict__ out_x) {
    int bx = blockIdx.x;
    if (bx < 8192) {
        int tid = threadIdx.x;
        int base = bx * 1024 + tid;
        int c4 = tid & 31;
        float4 rs = *(const float4*)(g_rs_e + 4 * c4);
        float4 of = *(const float4*)(g_ofs_e + 4 * c4);
        uint2 hv[4];
        float4 ev[4];
        #pragma unroll
        for (int q = 0; q < 4; q++) {
            hv[q] = __ldcs((const uint2*)g_enew + base + q * 256);  // dead after read
            ev[q] = __ldg((const float4*)e + base + q * 256);       // keep e in L2
        }
        #pragma unroll
        for (int q = 0; q < 4; q++) {
            float2 e01 = __half22float2(*reinterpret_cast<__half2*>(&hv[q].x));
            float2 e23 = __half22float2(*reinterpret_cast<__half2*>(&hv[q].y));
            float4 r = ev[q];
            r.x += fmaxf(fmaf(e01.x, rs.x, of.x), 0.f);
            r.y += fmaxf(fmaf(e01.y, rs.y, of.y), 0.f);
            r.z += fmaxf(fmaf(e23.x, rs.z, of.z), 0.f);
            r.w += fmaxf(fmaf(e23.y, rs.w, of.w), 0.f);
            __stcs((float4*)oe + base + q * 256, r);                // never re-read
        }
    } else if (bx < 8192 + 512) {
        int idx = (bx - 8192) * 256 + threadIdx.x;
        int ch = idx & 127;
        float v = fmaf(g_hpre[idx], g_rs_h[ch], g_ofs_h[ch]);
        out_h[idx] = h[idx] + fmaxf(v, 0.f);
    } else {
        __shared__ float rx[8], ry[8];
        int i = bx - 8192 - 512;      // node 0..1023
        int j = threadIdx.x;
        int lane = j & 31, wd = j >> 5;
        int b = i >> 8;
        float xi = x[i * 2], yi = x[i * 2 + 1];
        float pd = g_pd0[(size_t)i * Vn + j] + g_pd1[(size_t)i * Vn + j];
        float pa = sigmoidf_(pd + ebp[0]);
        float dx = xi - x[(b * Vn + j) * 2];
        float dy = yi - x[(b * Vn + j) * 2 + 1];
        float px = pa * dx, py = pa * dy;
        #pragma unroll
        for (int o = 16; o > 0; o >>= 1) {
            px += __shfl_xor_sync(0xffffffffu, px, o);
            py += __shfl_xor_sync(0xffffffffu, py, o);
        }
        if (lane == 0) { rx[wd] = px; ry[wd] = py; }
        __syncthreads();
        if (j == 0) {
            float sx = 0.f, sy = 0.f;
            #pragma unroll
            for (int w = 0; w < 8; w++) { sx += rx[w]; sy += ry[w]; }
            float c = cp[0];
            out_x[i * 2]     = xi + c * sx;
            out_x[i * 2 + 1] = yi + c * sy;
        }
    }
}

// ------------------------- launcher ---------------------------------------
extern "C" void kernel_launch(void* const* d_in, const int* in_sizes, int n_in,
                              void* d_out, int out_size) {
    const float* h     = (const float*)d_in[0];
    const float* e     = (const float*)d_in[1];
    const float* x     = (const float*)d_in[2];
    const int*   graph = (const int*)d_in[3];
    const float* Uw = (const float*)d_in[4],  *Ub = (const float*)d_in[5];
    const float* Vw = (const float*)d_in[6],  *Vb = (const float*)d_in[7];
    const float* Aw = (const float*)d_in[8],  *Ab = (const float*)d_in[9];
    const float* Bw = (const float*)d_in[10], *Bb = (const float*)d_in[11];
    const float* Cw = (const float*)d_in[12], *Cb = (const float*)d_in[13];
    const float* dwv = (const float*)d_in[14], *dbv = (const float*)d_in[15];
    const float* ewv = (const float*)d_in[16], *ebp = (const float*)d_in[17];
    const float* cp  = (const float*)d_in[18];
    const float* gh  = (const float*)d_in[19], *bh = (const float*)d_in[20];
    const float* ge  = (const float*)d_in[21], *be = (const float*)d_in[22];

    float* out_h = (float*)d_out;
    float* out_e = out_h + (size_t)BV * Hn;
    float* out_x = out_e + (size_t)NE * Hn;

    cudaFuncSetAttribute(k_main, cudaFuncAttributeMaxDynamicSharedMemorySize, SMEM_MAIN);

    k_pre<<<80, 256>>>(h, Cw, Uw, Ub, Vw, Vb, Aw, Ab, Bw, Bb);
    k_main<<<4096, 256, SMEM_MAIN>>>(e, x, graph, Cb, dwv, dbv, ewv);
    k_stats1<<<256, 128>>>();
    k_stats2<<<1, 512>>>(gh, bh, ge, be);
    k_finish<<<8192 + 512 + BV, 256>>>(e, out_e, h, out_h, x, cp, ebp, out_x);
}

// round 13
// speedup vs baseline: 1.9279x; 1.3700x over previous
#include <cuda_runtime.h>
#include <cuda_fp16.h>
#include <cstdint>

// Problem constants
#define Hn 128
#define Vn 256
#define BV 1024            // B*V node count
#define NE 262144          // B*V*V edge count

// ------------------------- device scratch --------------------------------
__device__ float g_Uh[BV * Hn];
__device__ float g_Vh[BV * Hn];
__device__ float g_Ah[BV * Hn];
__device__ float g_Bh[BV * Hn];
__device__ float g_hpre[BV * Hn];
__device__ float g_hpp[2048 * Hn];     // per-(i,jh) masked-aggregation partial
__device__ float g_ps[2048 * Hn];      // per-(i,jh) per-channel sum of e_new
__device__ float g_ps2[2048 * Hn];
__device__ float g_pd0[NE];            // pa-dot partial, n-half 0
__device__ float g_pd1[NE];            // pa-dot partial, n-half 1
__device__ float g_pse[256 * Hn], g_pse2[256 * Hn];   // stats partials
__device__ float g_psh[256 * Hn], g_psh2[256 * Hn];
__device__ float g_rs_e[Hn], g_ofs_e[Hn];
__device__ float g_rs_h[Hn], g_ofs_h[Hn];
__device__ uint8_t g_CwHi[32768];      // pre-swizzled fp16 Cw
__device__ __half g_enew[(size_t)NE * Hn];   // e_new in fp16 (64 MB)

__device__ __forceinline__ float sigmoidf_(float v) {
    return 1.0f / (1.0f + __expf(-v));
}

__device__ __forceinline__ uint32_t smem_u32(const void* p) {
    uint32_t a;
    asm("{ .reg .u64 t; cvta.to.shared.u64 t, %1; cvt.u32.u64 %0, t; }"
        : "=r"(a) : "l"(p));
    return a;
}

__device__ __forceinline__ uint32_t h2u(__half2 h) {
    return *reinterpret_cast<uint32_t*>(&h);
}

__device__ __forceinline__ __half2 u2h(uint32_t u) {
    return *reinterpret_cast<__half2*>(&u);
}

__device__ __forceinline__ void ldsm_x4(uint32_t& r0, uint32_t& r1, uint32_t& r2,
                                        uint32_t& r3, uint32_t addr) {
    asm volatile("ldmatrix.sync.aligned.m8n8.x4.shared.b16 {%0,%1,%2,%3}, [%4];"
                 : "=r"(r0), "=r"(r1), "=r"(r2), "=r"(r3) : "r"(addr));
}

__device__ __forceinline__ void mma16816(float* d, const uint32_t* a, const uint32_t* b) {
    asm volatile(
        "mma.sync.aligned.m16n8k16.row.col.f32.f16.f16.f32 "
        "{%0,%1,%2,%3}, {%4,%5,%6,%7}, {%8,%9}, {%0,%1,%2,%3};"
        : "+f"(d[0]), "+f"(d[1]), "+f"(d[2]), "+f"(d[3])
        : "r"(a[0]), "r"(a[1]), "r"(a[2]), "r"(a[3]), "r"(b[0]), "r"(b[1]));
}

__device__ __forceinline__ int sw_off(int idx /*float4 index*/) {
    int row = idx >> 5;
    int c4f = idx & 31;
    return row * 256 + (((c4f >> 1) ^ (row & 7)) << 4) + ((c4f & 1) << 3);
}

// ------------------------- K0: fused Cw prep + node linears ---------------
// grid 80: blocks 0..15 convert Cw, blocks 16..79 do node linears
__global__ void k_pre(const float* __restrict__ h, const float* __restrict__ Cw,
                      const float* __restrict__ Uw, const float* __restrict__ Ub,
                      const float* __restrict__ Vw, const float* __restrict__ Vb,
                      const float* __restrict__ Aw, const float* __restrict__ Ab,
                      const float* __restrict__ Bw, const float* __restrict__ Bb) {
    __shared__ float hs[16 * Hn];
    int tid = threadIdx.x;
    int bx = blockIdx.x;
    if (bx < 16) {
        int idx = bx * 256 + tid;     // 4096 float4s
        float4 v = __ldg((const float4*)Cw + idx);
        __half2 h0 = __floats2half2_rn(v.x, v.y);
        __half2 h1 = __floats2half2_rn(v.z, v.w);
        *(uint2*)(g_CwHi + sw_off(idx)) = make_uint2(h2u(h0), h2u(h1));
        return;
    }
    int row0 = (bx - 16) * 16;
    for (int idx = tid; idx < 16 * Hn; idx += 256)
        hs[idx] = h[(size_t)row0 * Hn + idx];
    __syncthreads();
    const float* Ws[4] = {Uw, Vw, Aw, Bw};
    const float* bs[4] = {Ub, Vb, Ab, Bb};
    float* outs[4];
    outs[0] = g_Uh; outs[1] = g_Vh; outs[2] = g_Ah; outs[3] = g_Bh;
    for (int p = 0; p < 2; p++) {
        int cid = tid + 256 * p;
        int m = cid >> 7;
        int o = cid & 127;
        const float* W = Ws[m] + (size_t)o * Hn;
        float acc[16];
        #pragma unroll
        for (int r = 0; r < 16; r++) acc[r] = 0.f;
        for (int k = 0; k < Hn; k += 4) {
            float4 w = *(const float4*)(W + k);
            #pragma unroll
            for (int r = 0; r < 16; r++) {
                acc[r] += hs[r * Hn + k] * w.x + hs[r * Hn + k + 1] * w.y +
                          hs[r * Hn + k + 2] * w.z + hs[r * Hn + k + 3] * w.w;
            }
        }
        float bias = bs[m][o];
        float* op = outs[m] + (size_t)row0 * Hn + o;
        #pragma unroll
        for (int r = 0; r < 16; r++) op[(size_t)r * Hn] = acc[r] + bias;
    }
}

// ------------------------- K1: main kernel (128j x 64n tile, fp16) --------
// grid 4096: blockIdx = ((i_glob*2 + jh)*2 + nh)
static constexpr int SA      = 0;      // 32768
static constexpr int SB      = 32768;  // 16384 -> 49152
// post-MMA aliases:
static constexpr int SM_STG  = 0;      // 128 x 32 uint32 (fp16 stage) = 16384
static constexpr int SM_PD   = 16384;  // 128 x 17 f = 8704 (inside SA)
static constexpr int SM_RPS  = 32768;  // 16x64 f -> 36864
static constexpr int SM_RPS2 = 36864;  // -> 40960
static constexpr int SM_RM   = 40960;  // -> 45056 (inside SB)
// persistent misc:
static constexpr int SM_BC   = 49152;  // 128 f
static constexpr int SM_DW   = 49664;
static constexpr int SM_EW   = 50176;
static constexpr int SM_DIST = 50688;
static constexpr int SM_GR   = 51200;  // -> 51712
static constexpr int SMEM_MAIN = 51712;

__global__ void __launch_bounds__(256, 4)
k_main(const float* __restrict__ e, const float* __restrict__ x,
       const int* __restrict__ graph, const float* __restrict__ Cb,
       const float* __restrict__ dwv, const float* __restrict__ dbv,
       const float* __restrict__ ewv) {
    extern __shared__ char sm[];
    uint32_t smb = smem_u32(sm);
    int tid = threadIdx.x;
    int wid = tid >> 5;
    int lane = tid & 31;

    int bx = blockIdx.x;
    int i_glob = bx >> 2;          // b*V + i
    int jh = (bx >> 1) & 1;
    int nh = bx & 1;
    int b = i_glob >> 8;
    int jbase = jh * 128;

    float* sBC   = (float*)(sm + SM_BC);
    float* sdw   = (float*)(sm + SM_DW);
    float* sew   = (float*)(sm + SM_EW);
    float* sdist = (float*)(sm + SM_DIST);
    int*   sgr   = (int*)(sm + SM_GR);
    float* spd   = (float*)(sm + SM_PD);
    float* rps   = (float*)(sm + SM_RPS);
    float* rps2  = (float*)(sm + SM_RPS2);
    float* rmm   = (float*)(sm + SM_RM);

    float xi = x[i_glob * 2], yi = x[i_glob * 2 + 1];
    if (tid < 128) {
        sBC[tid] = g_Bh[(size_t)i_glob * Hn + tid] + Cb[tid] + dbv[tid];
        sdw[tid] = dwv[tid];
        sew[tid] = ewv[tid];
        int jg = jbase + tid;
        float dx = xi - x[(b * Vn + jg) * 2];
        float dy = yi - x[(b * Vn + jg) * 2 + 1];
        float d2 = dx * dx + dy * dy;
        sdist[tid] = d2 > 0.f ? sqrtf(d2) : 0.f;
        sgr[tid] = graph[(size_t)i_glob * Vn + jg];
    }

    // A: load + convert e tile (128x128) to fp16
    {
        const float4* src = (const float4*)(e + ((size_t)i_glob * Vn + jbase) * Hn);
        #pragma unroll
        for (int q = 0; q < 16; q++) {
            int idx = tid + 256 * q;
            float4 v = __ldg(src + idx);
            __half2 h0 = __floats2half2_rn(v.x, v.y);
            __half2 h1 = __floats2half2_rn(v.z, v.w);
            *(uint2*)(sm + SA + sw_off(idx)) = make_uint2(h2u(h0), h2u(h1));
        }
    }
    // B: straight copy of pre-converted Cw rows [nh*64, nh*64+64)
    {
        const uint4* srcH = (const uint4*)(g_CwHi) + nh * 1024;
        uint4* dstH = (uint4*)(sm + SB);
        #pragma unroll
        for (int t = tid; t < 1024; t += 256)
            dstH[t] = __ldg(srcH + t);
    }
    __syncthreads();

    // ---- MMA: warp grid 4(m) x 2(n); warp tile 32x32 ----
    int wm = wid & 3;
    int wn = wid >> 2;

    float acc[2][4][4];
    #pragma unroll
    for (int mi = 0; mi < 2; mi++)
        #pragma unroll
        for (int ni = 0; ni < 4; ni++)
            #pragma unroll
            for (int c = 0; c < 4; c++) acc[mi][ni][c] = 0.f;

    int la7 = lane & 7;
    int rowA_base = wm * 32 + la7 + ((lane >> 3) & 1) * 8;
    int a_ch = lane >> 4;
    int b_tile = lane >> 3;
    int b_nip = b_tile >> 1;
    int b_ch = b_tile & 1;
    int rowB_lane = wn * 32 + la7;

    #pragma unroll
    for (int ks = 0; ks < 8; ks++) {
        uint32_t ah[2][4];
        #pragma unroll
        for (int mi = 0; mi < 2; mi++) {
            int r = rowA_base + mi * 16;
            uint32_t off = r * 256 + (((ks * 2 + a_ch) ^ (r & 7)) << 4);
            ldsm_x4(ah[mi][0], ah[mi][1], ah[mi][2], ah[mi][3], smb + SA + off);
        }
        uint32_t bh[4][2];
        #pragma unroll
        for (int p = 0; p < 2; p++) {
            int r = rowB_lane + (p * 2 + b_nip) * 8;
            uint32_t off = r * 256 + (((ks * 2 + b_ch) ^ (r & 7)) << 4);
            ldsm_x4(bh[p * 2][0], bh[p * 2][1], bh[p * 2 + 1][0], bh[p * 2 + 1][1],
                    smb + SB + off);
        }
        #pragma unroll
        for (int mi = 0; mi < 2; mi++)
            #pragma unroll
            for (int ni = 0; ni < 4; ni++)
                mma16816(acc[mi][ni], ah[mi], bh[ni]);
    }
    __syncthreads();   // MMA done: SA -> stage+pd, SB -> reductions

    // ---- stage accumulators as fp16 into SM_STG (128 rows x 32 half2) ----
    uint32_t* stage16 = (uint32_t*)(sm + SM_STG);
    {
        #pragma unroll
        for (int mi = 0; mi < 2; mi++) {
            #pragma unroll
            for (int rh = 0; rh < 2; rh++) {
                int r = wm * 32 + mi * 16 + (lane >> 2) + rh * 8;
                int sx = (r & 7) << 2;
                #pragma unroll
                for (int ni = 0; ni < 4; ni++) {
                    int hc = wn * 16 + ni * 4 + (lane & 3);
                    __half2 hp = __floats2half2_rn(acc[mi][ni][rh * 2],
                                                   acc[mi][ni][rh * 2 + 1]);
                    stage16[r * 32 + (hc ^ sx)] = h2u(hp);
                }
            }
        }
    }
    __syncthreads();

    // ---- coalesced epilogue: thread = (row-group rg, col-group cg4) ----
    int cg4 = tid & 15;
    int rg  = tid >> 4;
    int cgl = cg4 * 4;
    int cgg = nh * 64 + cgl;
    float4 bc4 = *(const float4*)(sBC + cgg);
    float4 dw4 = *(const float4*)(sdw + cgg);
    float4 ew4 = *(const float4*)(sew + cgg);
    float4 cs  = make_float4(0.f, 0.f, 0.f, 0.f);
    float4 cq  = make_float4(0.f, 0.f, 0.f, 0.f);
    float4 cm  = make_float4(0.f, 0.f, 0.f, 0.f);

    __half* eh = g_enew + ((size_t)i_glob * Vn + jbase) * Hn;

    #pragma unroll
    for (int k = 0; k < 8; k++) {
        int r = rg + 16 * k;
        int hc2 = (cg4 * 2) ^ ((r & 7) << 2);
        uint2 sv = *(const uint2*)(stage16 + r * 32 + hc2);
        float2 f01 = __half22float2(u2h(sv.x));
        float2 f23 = __half22float2(u2h(sv.y));
        size_t nrow = ((size_t)(b * Vn + jbase + r)) * Hn + cgg;
        float4 a  = __ldg((const float4*)(g_Ah + nrow));
        float4 vh = __ldg((const float4*)(g_Vh + nrow));
        float dist = sdist[r];
        bool keep = (sgr[r] != 1);
        float t0 = f01.x + a.x + bc4.x + dist * dw4.x;
        float t1 = f01.y + a.y + bc4.y + dist * dw4.y;
        float t2 = f23.x + a.z + bc4.z + dist * dw4.z;
        float t3 = f23.y + a.w + bc4.w + dist * dw4.w;
        __half2 p0 = __floats2half2_rn(t0, t1);
        __half2 p1 = __floats2half2_rn(t2, t3);
        *(uint2*)(eh + (size_t)r * Hn + cgg) = make_uint2(h2u(p0), h2u(p1));
        cs.x += t0; cs.y += t1; cs.z += t2; cs.w += t3;
        cq.x += t0 * t0; cq.y += t1 * t1; cq.z += t2 * t2; cq.w += t3 * t3;
        if (keep) {
            cm.x += sigmoidf_(t0) * vh.x;
            cm.y += sigmoidf_(t1) * vh.y;
            cm.z += sigmoidf_(t2) * vh.z;
            cm.w += sigmoidf_(t3) * vh.w;
        }
        spd[r * 17 + cg4] = t0 * ew4.x + t1 * ew4.y + t2 * ew4.z + t3 * ew4.w;
    }

    *(float4*)(rps  + rg * 64 + cgl) = cs;
    *(float4*)(rps2 + rg * 64 + cgl) = cq;
    *(float4*)(rmm  + rg * 64 + cgl) = cm;
    __syncthreads();

    if (tid < 64) {
        float s = 0.f, s2 = 0.f, mm = 0.f;
        #pragma unroll
        for (int g = 0; g < 16; g++) {
            s  += rps[g * 64 + tid];
            s2 += rps2[g * 64 + tid];
            mm += rmm[g * 64 + tid];
        }
        size_t gi = ((size_t)i_glob * 2 + jh) * Hn + nh * 64 + tid;
        g_ps[gi]  = s;
        g_ps2[gi] = s2;
        g_hpp[gi] = mm;
    }
    if (tid >= 128) {
        int r = tid - 128;
        float pdt = 0.f;
        #pragma unroll
        for (int q = 0; q < 16; q++) pdt += spd[r * 17 + q];
        float* gpd = nh ? g_pd1 : g_pd0;
        gpd[(size_t)i_glob * Vn + jbase + r] = pdt;
    }
}

// ------------------------- K2a: stats partials ----------------------------
__global__ void __launch_bounds__(128)
k_stats1() {
    int ch = threadIdx.x;
    int c = blockIdx.x;        // 256 blocks, 4 nodes each
    double se = 0.0, se2 = 0.0, sh = 0.0, sh2 = 0.0;
    for (int i = c * 4; i < c * 4 + 4; i++) {
        float hv = g_Uh[(size_t)i * Hn + ch] +
                   g_hpp[(size_t)(2 * i) * Hn + ch] +
                   g_hpp[(size_t)(2 * i + 1) * Hn + ch];
        g_hpre[(size_t)i * Hn + ch] = hv;
        sh += (double)hv; sh2 += (double)hv * (double)hv;
        se  += (double)g_ps[(size_t)(2 * i) * Hn + ch]  + (double)g_ps[(size_t)(2 * i + 1) * Hn + ch];
        se2 += (double)g_ps2[(size_t)(2 * i) * Hn + ch] + (double)g_ps2[(size_t)(2 * i + 1) * Hn + ch];
    }
    g_pse[c * Hn + ch]  = (float)se;
    g_pse2[c * Hn + ch] = (float)se2;
    g_psh[c * Hn + ch]  = (float)sh;
    g_psh2[c * Hn + ch] = (float)sh2;
}

// ------------------------- K2b: stats finalize (parallel, 1 block/channel) -
__global__ void __launch_bounds__(256)
k_stats2(const float* __restrict__ gamma_h, const float* __restrict__ beta_h,
         const float* __restrict__ gamma_e, const float* __restrict__ beta_e) {
    __shared__ double sde[256], sde2[256], sdh[256], sdh2[256];
    int ch = blockIdx.x;       // 128 blocks, one per channel
    int t = threadIdx.x;       // 256 partials, one per thread
    sde[t]  = (double)g_pse[t * Hn + ch];
    sde2[t] = (double)g_pse2[t * Hn + ch];
    sdh[t]  = (double)g_psh[t * Hn + ch];
    sdh2[t] = (double)g_psh2[t * Hn + ch];
    __syncthreads();
    #pragma unroll
    for (int s = 128; s > 0; s >>= 1) {
        if (t < s) {
            sde[t]  += sde[t + s];
            sde2[t] += sde2[t + s];
            sdh[t]  += sdh[t + s];
            sdh2[t] += sdh2[t + s];
        }
        __syncthreads();
    }
    if (t == 0) {
        float mu  = (float)(sde[0] / (double)NE);
        float var = (float)(sde2[0] / (double)NE) - mu * mu;
        float rs = gamma_e[ch] * rsqrtf(var + 1e-5f);
        g_rs_e[ch] = rs;
        g_ofs_e[ch] = beta_e[ch] - mu * rs;

        float muh  = (float)(sdh[0] / (double)BV);
        float varh = (float)(sdh2[0] / (double)BV) - muh * muh;
        float rsh = gamma_h[ch] * rsqrtf(varh + 1e-5f);
        g_rs_h[ch] = rsh;
        g_ofs_h[ch] = beta_h[ch] - muh * rsh;
    }
}

// ------------------------- K3: fused finish (e / h / x) -------------------
__global__ void __launch_bounds__(256)
k_finish(const float* __restrict__ e, float* __restrict__ oe,
         const float* __restrict__ h, float* __restrict__ out_h,
         const float* __restrict__ x, const float* __restrict__ cp,
         const float* __restrict__ ebp, float* __restrict__ out_x) {
    int bx = blockIdx.x;
    if (bx < 8192) {
        int tid = threadIdx.x;
        int base = bx * 1024 + tid;
        int c4 = tid & 31;
        float4 rs = *(const float4*)(g_rs_e + 4 * c4);
        float4 of = *(const float4*)(g_ofs_e + 4 * c4);
        uint2 hv[4];
        float4 ev[4];
        #pragma unroll
        for (int q = 0; q < 4; q++) {
            hv[q] = __ldcs((const uint2*)g_enew + base + q * 256);  // dead after read
            ev[q] = __ldg((const float4*)e + base + q * 256);       // keep e in L2
        }
        #pragma unroll
        for (int q = 0; q < 4; q++) {
            float2 e01 = __half22float2(*reinterpret_cast<__half2*>(&hv[q].x));
            float2 e23 = __half22float2(*reinterpret_cast<__half2*>(&hv[q].y));
            float4 r = ev[q];
            r.x += fmaxf(fmaf(e01.x, rs.x, of.x), 0.f);
            r.y += fmaxf(fmaf(e01.y, rs.y, of.y), 0.f);
            r.z += fmaxf(fmaf(e23.x, rs.z, of.z), 0.f);
            r.w += fmaxf(fmaf(e23.y, rs.w, of.w), 0.f);
            __stcs((float4*)oe + base + q * 256, r);                // never re-read
        }
    } else if (bx < 8192 + 512) {
        int idx = (bx - 8192) * 256 + threadIdx.x;
        int ch = idx & 127;
        float v = fmaf(g_hpre[idx], g_rs_h[ch], g_ofs_h[ch]);
        out_h[idx] = h[idx] + fmaxf(v, 0.f);
    } else {
        __shared__ float rx[8], ry[8];
        int i = bx - 8192 - 512;      // node 0..1023
        int j = threadIdx.x;
        int lane = j & 31, wd = j >> 5;
        int b = i >> 8;
        float xi = x[i * 2], yi = x[i * 2 + 1];
        float pd = g_pd0[(size_t)i * Vn + j] + g_pd1[(size_t)i * Vn + j];
        float pa = sigmoidf_(pd + ebp[0]);
        float dx = xi - x[(b * Vn + j) * 2];
        float dy = yi - x[(b * Vn + j) * 2 + 1];
        float px = pa * dx, py = pa * dy;
        #pragma unroll
        for (int o = 16; o > 0; o >>= 1) {
            px += __shfl_xor_sync(0xffffffffu, px, o);
            py += __shfl_xor_sync(0xffffffffu, py, o);
        }
        if (lane == 0) { rx[wd] = px; ry[wd] = py; }
        __syncthreads();
        if (j == 0) {
            float sx = 0.f, sy = 0.f;
            #pragma unroll
            for (int w = 0; w < 8; w++) { sx += rx[w]; sy += ry[w]; }
            float c = cp[0];
            out_x[i * 2]     = xi + c * sx;
            out_x[i * 2 + 1] = yi + c * sy;
        }
    }
}

// ------------------------- launcher ---------------------------------------
extern "C" void kernel_launch(void* const* d_in, const int* in_sizes, int n_in,
                              void* d_out, int out_size) {
    const float* h     = (const float*)d_in[0];
    const float* e     = (const float*)d_in[1];
    const float* x     = (const float*)d_in[2];
    const int*   graph = (const int*)d_in[3];
    const float* Uw = (const float*)d_in[4],  *Ub = (const float*)d_in[5];
    const float* Vw = (const float*)d_in[6],  *Vb = (const float*)d_in[7];
    const float* Aw = (const float*)d_in[8],  *Ab = (const float*)d_in[9];
    const float* Bw = (const float*)d_in[10], *Bb = (const float*)d_in[11];
    const float* Cw = (const float*)d_in[12], *Cb = (const float*)d_in[13];
    const float* dwv = (const float*)d_in[14], *dbv = (const float*)d_in[15];
    const float* ewv = (const float*)d_in[16], *ebp = (const float*)d_in[17];
    const float* cp  = (const float*)d_in[18];
    const float* gh  = (const float*)d_in[19], *bh = (const float*)d_in[20];
    const float* ge  = (const float*)d_in[21], *be = (const float*)d_in[22];

    float* out_h = (float*)d_out;
    float* out_e = out_h + (size_t)BV * Hn;
    float* out_x = out_e + (size_t)NE * Hn;

    cudaFuncSetAttribute(k_main, cudaFuncAttributeMaxDynamicSharedMemorySize, SMEM_MAIN);

    k_pre<<<80, 256>>>(h, Cw, Uw, Ub, Vw, Vb, Aw, Ab, Bw, Bb);
    k_main<<<4096, 256, SMEM_MAIN>>>(e, x, graph, Cb, dwv, dbv, ewv);
    k_stats1<<<256, 128>>>();
    k_stats2<<<128, 256>>>(gh, bh, ge, be);
    k_finish<<<8192 + 512 + BV, 256>>>(e, out_e, h, out_h, x, cp, ebp, out_x);
}

// round 14
// speedup vs baseline: 2.0154x; 1.0454x over previous
#include <cuda_runtime.h>
#include <cuda_fp16.h>
#include <cstdint>

// Problem constants
#define Hn 128
#define Vn 256
#define BV 1024            // B*V node count
#define NE 262144          // B*V*V edge count

// ------------------------- device scratch --------------------------------
__device__ float g_Uh[BV * Hn];
__device__ float g_Vh[BV * Hn];
__device__ float g_Ah[BV * Hn];
__device__ float g_Bh[BV * Hn];
__device__ float g_hpre[BV * Hn];
__device__ float g_hpp[2048 * Hn];     // per-(i,jh) masked-aggregation partial
__device__ float g_ps[2048 * Hn];      // per-(i,jh) per-channel sum of e_new
__device__ float g_ps2[2048 * Hn];
__device__ float g_pd0[NE];            // pa-dot partial, n-half 0
__device__ float g_pd1[NE];            // pa-dot partial, n-half 1
__device__ float g_pse[1024 * Hn], g_pse2[1024 * Hn];   // stats partials (per node)
__device__ float g_psh[1024 * Hn], g_psh2[1024 * Hn];
__device__ float g_rs_e[Hn], g_ofs_e[Hn];
__device__ float g_rs_h[Hn], g_ofs_h[Hn];
__device__ uint8_t g_CwHi[32768];      // pre-swizzled fp16 Cw
__device__ __half g_enew[(size_t)NE * Hn];   // e_new in fp16 (64 MB)

__device__ __forceinline__ float sigmoidf_(float v) {
    return 1.0f / (1.0f + __expf(-v));
}

__device__ __forceinline__ uint32_t smem_u32(const void* p) {
    uint32_t a;
    asm("{ .reg .u64 t; cvta.to.shared.u64 t, %1; cvt.u32.u64 %0, t; }"
        : "=r"(a) : "l"(p));
    return a;
}

__device__ __forceinline__ uint32_t h2u(__half2 h) {
    return *reinterpret_cast<uint32_t*>(&h);
}

__device__ __forceinline__ __half2 u2h(uint32_t u) {
    return *reinterpret_cast<__half2*>(&u);
}

__device__ __forceinline__ void ldsm_x4(uint32_t& r0, uint32_t& r1, uint32_t& r2,
                                        uint32_t& r3, uint32_t addr) {
    asm volatile("ldmatrix.sync.aligned.m8n8.x4.shared.b16 {%0,%1,%2,%3}, [%4];"
                 : "=r"(r0), "=r"(r1), "=r"(r2), "=r"(r3) : "r"(addr));
}

__device__ __forceinline__ void mma16816(float* d, const uint32_t* a, const uint32_t* b) {
    asm volatile(
        "mma.sync.aligned.m16n8k16.row.col.f32.f16.f16.f32 "
        "{%0,%1,%2,%3}, {%4,%5,%6,%7}, {%8,%9}, {%0,%1,%2,%3};"
        : "+f"(d[0]), "+f"(d[1]), "+f"(d[2]), "+f"(d[3])
        : "r"(a[0]), "r"(a[1]), "r"(a[2]), "r"(a[3]), "r"(b[0]), "r"(b[1]));
}

__device__ __forceinline__ int sw_off(int idx /*float4 index*/) {
    int row = idx >> 5;
    int c4f = idx & 31;
    return row * 256 + (((c4f >> 1) ^ (row & 7)) << 4) + ((c4f & 1) << 3);
}

// ------------------------- K0: fused Cw prep + node linears ---------------
// grid 272: blocks 0..15 convert Cw; blocks 16..271 = (matrix, 16-row block)
__global__ void __launch_bounds__(256)
k_pre(const float* __restrict__ h, const float* __restrict__ Cw,
      const float* __restrict__ Uw, const float* __restrict__ Ub,
      const float* __restrict__ Vw, const float* __restrict__ Vb,
      const float* __restrict__ Aw, const float* __restrict__ Ab,
      const float* __restrict__ Bw, const float* __restrict__ Bb) {
    __shared__ float hs[16 * Hn];
    int tid = threadIdx.x;
    int bx = blockIdx.x;
    if (bx < 16) {
        int idx = bx * 256 + tid;     // 4096 float4s
        float4 v = __ldg((const float4*)Cw + idx);
        __half2 h0 = __floats2half2_rn(v.x, v.y);
        __half2 h1 = __floats2half2_rn(v.z, v.w);
        *(uint2*)(g_CwHi + sw_off(idx)) = make_uint2(h2u(h0), h2u(h1));
        return;
    }
    int bx2 = bx - 16;                // 0..255
    int m = bx2 & 3;                  // matrix id
    int row0 = (bx2 >> 2) * 16;       // 16-row block
    for (int idx = tid; idx < 16 * Hn; idx += 256)
        hs[idx] = h[(size_t)row0 * Hn + idx];
    __syncthreads();
    const float* Ws[4] = {Uw, Vw, Aw, Bw};
    const float* bs[4] = {Ub, Vb, Ab, Bb};
    float* outs[4];
    outs[0] = g_Uh; outs[1] = g_Vh; outs[2] = g_Ah; outs[3] = g_Bh;

    int half = tid >> 7;              // 0/1 -> rows [half*8, half*8+8)
    int o = tid & 127;
    const float* W = Ws[m] + (size_t)o * Hn;
    float acc[8];
    #pragma unroll
    for (int r = 0; r < 8; r++) acc[r] = 0.f;
    const float* hrow = hs + half * 8 * Hn;
    for (int k = 0; k < Hn; k += 4) {
        float4 w = *(const float4*)(W + k);
        #pragma unroll
        for (int r = 0; r < 8; r++) {
            acc[r] += hrow[r * Hn + k] * w.x + hrow[r * Hn + k + 1] * w.y +
                      hrow[r * Hn + k + 2] * w.z + hrow[r * Hn + k + 3] * w.w;
        }
    }
    float bias = bs[m][o];
    float* op = outs[m] + (size_t)(row0 + half * 8) * Hn + o;
    #pragma unroll
    for (int r = 0; r < 8; r++) op[(size_t)r * Hn] = acc[r] + bias;
}

// ------------------------- K1: main kernel (128j x 64n tile, fp16) --------
// grid 4096: blockIdx = ((i_glob*2 + jh)*2 + nh)
static constexpr int SA      = 0;      // 32768
static constexpr int SB      = 32768;  // 16384 -> 49152
// post-MMA aliases:
static constexpr int SM_STG  = 0;      // 128 x 32 uint32 (fp16 stage) = 16384
static constexpr int SM_PD   = 16384;  // 128 x 17 f = 8704 (inside SA)
static constexpr int SM_RPS  = 32768;  // 16x64 f -> 36864
static constexpr int SM_RPS2 = 36864;  // -> 40960
static constexpr int SM_RM   = 40960;  // -> 45056 (inside SB)
// persistent misc:
static constexpr int SM_BC   = 49152;  // 128 f
static constexpr int SM_DW   = 49664;
static constexpr int SM_EW   = 50176;
static constexpr int SM_DIST = 50688;
static constexpr int SM_GR   = 51200;  // -> 51712
static constexpr int SMEM_MAIN = 51712;

__global__ void __launch_bounds__(256, 4)
k_main(const float* __restrict__ e, const float* __restrict__ x,
       const int* __restrict__ graph, const float* __restrict__ Cb,
       const float* __restrict__ dwv, const float* __restrict__ dbv,
       const float* __restrict__ ewv) {
    extern __shared__ char sm[];
    uint32_t smb = smem_u32(sm);
    int tid = threadIdx.x;
    int wid = tid >> 5;
    int lane = tid & 31;

    int bx = blockIdx.x;
    int i_glob = bx >> 2;          // b*V + i
    int jh = (bx >> 1) & 1;
    int nh = bx & 1;
    int b = i_glob >> 8;
    int jbase = jh * 128;

    float* sBC   = (float*)(sm + SM_BC);
    float* sdw   = (float*)(sm + SM_DW);
    float* sew   = (float*)(sm + SM_EW);
    float* sdist = (float*)(sm + SM_DIST);
    int*   sgr   = (int*)(sm + SM_GR);
    float* spd   = (float*)(sm + SM_PD);
    float* rps   = (float*)(sm + SM_RPS);
    float* rps2  = (float*)(sm + SM_RPS2);
    float* rmm   = (float*)(sm + SM_RM);

    float xi = x[i_glob * 2], yi = x[i_glob * 2 + 1];
    if (tid < 128) {
        sBC[tid] = g_Bh[(size_t)i_glob * Hn + tid] + Cb[tid] + dbv[tid];
        sdw[tid] = dwv[tid];
        sew[tid] = ewv[tid];
        int jg = jbase + tid;
        float dx = xi - x[(b * Vn + jg) * 2];
        float dy = yi - x[(b * Vn + jg) * 2 + 1];
        float d2 = dx * dx + dy * dy;
        sdist[tid] = d2 > 0.f ? sqrtf(d2) : 0.f;
        sgr[tid] = graph[(size_t)i_glob * Vn + jg];
    }

    // A: load + convert e tile (128x128) to fp16
    {
        const float4* src = (const float4*)(e + ((size_t)i_glob * Vn + jbase) * Hn);
        #pragma unroll
        for (int q = 0; q < 16; q++) {
            int idx = tid + 256 * q;
            float4 v = __ldg(src + idx);
            __half2 h0 = __floats2half2_rn(v.x, v.y);
            __half2 h1 = __floats2half2_rn(v.z, v.w);
            *(uint2*)(sm + SA + sw_off(idx)) = make_uint2(h2u(h0), h2u(h1));
        }
    }
    // B: straight copy of pre-converted Cw rows [nh*64, nh*64+64)
    {
        const uint4* srcH = (const uint4*)(g_CwHi) + nh * 1024;
        uint4* dstH = (uint4*)(sm + SB);
        #pragma unroll
        for (int t = tid; t < 1024; t += 256)
            dstH[t] = __ldg(srcH + t);
    }
    __syncthreads();

    // ---- MMA: warp grid 4(m) x 2(n); warp tile 32x32 ----
    int wm = wid & 3;
    int wn = wid >> 2;

    float acc[2][4][4];
    #pragma unroll
    for (int mi = 0; mi < 2; mi++)
        #pragma unroll
        for (int ni = 0; ni < 4; ni++)
            #pragma unroll
            for (int c = 0; c < 4; c++) acc[mi][ni][c] = 0.f;

    int la7 = lane & 7;
    int rowA_base = wm * 32 + la7 + ((lane >> 3) & 1) * 8;
    int a_ch = lane >> 4;
    int b_tile = lane >> 3;
    int b_nip = b_tile >> 1;
    int b_ch = b_tile & 1;
    int rowB_lane = wn * 32 + la7;

    #pragma unroll
    for (int ks = 0; ks < 8; ks++) {
        uint32_t ah[2][4];
        #pragma unroll
        for (int mi = 0; mi < 2; mi++) {
            int r = rowA_base + mi * 16;
            uint32_t off = r * 256 + (((ks * 2 + a_ch) ^ (r & 7)) << 4);
            ldsm_x4(ah[mi][0], ah[mi][1], ah[mi][2], ah[mi][3], smb + SA + off);
        }
        uint32_t bh[4][2];
        #pragma unroll
        for (int p = 0; p < 2; p++) {
            int r = rowB_lane + (p * 2 + b_nip) * 8;
            uint32_t off = r * 256 + (((ks * 2 + b_ch) ^ (r & 7)) << 4);
            ldsm_x4(bh[p * 2][0], bh[p * 2][1], bh[p * 2 + 1][0], bh[p * 2 + 1][1],
                    smb + SB + off);
        }
        #pragma unroll
        for (int mi = 0; mi < 2; mi++)
            #pragma unroll
            for (int ni = 0; ni < 4; ni++)
                mma16816(acc[mi][ni], ah[mi], bh[ni]);
    }
    __syncthreads();   // MMA done: SA -> stage+pd, SB -> reductions

    // ---- stage accumulators as fp16 into SM_STG (128 rows x 32 half2) ----
    uint32_t* stage16 = (uint32_t*)(sm + SM_STG);
    {
        #pragma unroll
        for (int mi = 0; mi < 2; mi++) {
            #pragma unroll
            for (int rh = 0; rh < 2; rh++) {
                int r = wm * 32 + mi * 16 + (lane >> 2) + rh * 8;
                int sx = (r & 7) << 2;
                #pragma unroll
                for (int ni = 0; ni < 4; ni++) {
                    int hc = wn * 16 + ni * 4 + (lane & 3);
                    __half2 hp = __floats2half2_rn(acc[mi][ni][rh * 2],
                                                   acc[mi][ni][rh * 2 + 1]);
                    stage16[r * 32 + (hc ^ sx)] = h2u(hp);
                }
            }
        }
    }
    __syncthreads();

    // ---- coalesced epilogue: thread = (row-group rg, col-group cg4) ----
    int cg4 = tid & 15;
    int rg  = tid >> 4;
    int cgl = cg4 * 4;
    int cgg = nh * 64 + cgl;
    float4 bc4 = *(const float4*)(sBC + cgg);
    float4 dw4 = *(const float4*)(sdw + cgg);
    float4 ew4 = *(const float4*)(sew + cgg);
    float4 cs  = make_float4(0.f, 0.f, 0.f, 0.f);
    float4 cq  = make_float4(0.f, 0.f, 0.f, 0.f);
    float4 cm  = make_float4(0.f, 0.f, 0.f, 0.f);

    __half* eh = g_enew + ((size_t)i_glob * Vn + jbase) * Hn;

    #pragma unroll
    for (int k = 0; k < 8; k++) {
        int r = rg + 16 * k;
        int hc2 = (cg4 * 2) ^ ((r & 7) << 2);
        uint2 sv = *(const uint2*)(stage16 + r * 32 + hc2);
        float2 f01 = __half22float2(u2h(sv.x));
        float2 f23 = __half22float2(u2h(sv.y));
        size_t nrow = ((size_t)(b * Vn + jbase + r)) * Hn + cgg;
        float4 a  = __ldg((const float4*)(g_Ah + nrow));
        float4 vh = __ldg((const float4*)(g_Vh + nrow));
        float dist = sdist[r];
        bool keep = (sgr[r] != 1);
        float t0 = f01.x + a.x + bc4.x + dist * dw4.x;
        float t1 = f01.y + a.y + bc4.y + dist * dw4.y;
        float t2 = f23.x + a.z + bc4.z + dist * dw4.z;
        float t3 = f23.y + a.w + bc4.w + dist * dw4.w;
        __half2 p0 = __floats2half2_rn(t0, t1);
        __half2 p1 = __floats2half2_rn(t2, t3);
        *(uint2*)(eh + (size_t)r * Hn + cgg) = make_uint2(h2u(p0), h2u(p1));
        cs.x += t0; cs.y += t1; cs.z += t2; cs.w += t3;
        cq.x += t0 * t0; cq.y += t1 * t1; cq.z += t2 * t2; cq.w += t3 * t3;
        if (keep) {
            cm.x += sigmoidf_(t0) * vh.x;
            cm.y += sigmoidf_(t1) * vh.y;
            cm.z += sigmoidf_(t2) * vh.z;
            cm.w += sigmoidf_(t3) * vh.w;
        }
        spd[r * 17 + cg4] = t0 * ew4.x + t1 * ew4.y + t2 * ew4.z + t3 * ew4.w;
    }

    *(float4*)(rps  + rg * 64 + cgl) = cs;
    *(float4*)(rps2 + rg * 64 + cgl) = cq;
    *(float4*)(rmm  + rg * 64 + cgl) = cm;
    __syncthreads();

    if (tid < 64) {
        float s = 0.f, s2 = 0.f, mm = 0.f;
        #pragma unroll
        for (int g = 0; g < 16; g++) {
            s  += rps[g * 64 + tid];
            s2 += rps2[g * 64 + tid];
            mm += rmm[g * 64 + tid];
        }
        size_t gi = ((size_t)i_glob * 2 + jh) * Hn + nh * 64 + tid;
        g_ps[gi]  = s;
        g_ps2[gi] = s2;
        g_hpp[gi] = mm;
    }
    if (tid >= 128) {
        int r = tid - 128;
        float pdt = 0.f;
        #pragma unroll
        for (int q = 0; q < 16; q++) pdt += spd[r * 17 + q];
        float* gpd = nh ? g_pd1 : g_pd0;
        gpd[(size_t)i_glob * Vn + jbase + r] = pdt;
    }
}

// ------------------------- K2a: stats partials (1 block per node) ---------
__global__ void __launch_bounds__(128)
k_stats1() {
    int ch = threadIdx.x;
    int i = blockIdx.x;        // 1024 blocks, one node each
    float p0  = g_ps[(size_t)(2 * i) * Hn + ch];
    float p1  = g_ps[(size_t)(2 * i + 1) * Hn + ch];
    float q0  = g_ps2[(size_t)(2 * i) * Hn + ch];
    float q1  = g_ps2[(size_t)(2 * i + 1) * Hn + ch];
    float m0  = g_hpp[(size_t)(2 * i) * Hn + ch];
    float m1  = g_hpp[(size_t)(2 * i + 1) * Hn + ch];
    float hv = g_Uh[(size_t)i * Hn + ch] + m0 + m1;
    g_hpre[(size_t)i * Hn + ch] = hv;
    g_pse[(size_t)i * Hn + ch]  = p0 + p1;
    g_pse2[(size_t)i * Hn + ch] = q0 + q1;
    g_psh[(size_t)i * Hn + ch]  = hv;
    g_psh2[(size_t)i * Hn + ch] = hv * hv;
}

// ------------------------- K2b: stats finalize (1 block per channel) ------
__global__ void __launch_bounds__(256)
k_stats2(const float* __restrict__ gamma_h, const float* __restrict__ beta_h,
         const float* __restrict__ gamma_e, const float* __restrict__ beta_e) {
    __shared__ double sde[256], sde2[256], sdh[256], sdh2[256];
    int ch = blockIdx.x;       // 128 blocks, one per channel
    int t = threadIdx.x;
    double se = 0.0, se2 = 0.0, sh = 0.0, sh2 = 0.0;
    #pragma unroll
    for (int q = 0; q < 4; q++) {
        int p = t + q * 256;   // 1024 partials
        se  += (double)g_pse[(size_t)p * Hn + ch];
        se2 += (double)g_pse2[(size_t)p * Hn + ch];
        sh  += (double)g_psh[(size_t)p * Hn + ch];
        sh2 += (double)g_psh2[(size_t)p * Hn + ch];
    }
    sde[t] = se; sde2[t] = se2; sdh[t] = sh; sdh2[t] = sh2;
    __syncthreads();
    #pragma unroll
    for (int s = 128; s > 0; s >>= 1) {
        if (t < s) {
            sde[t]  += sde[t + s];
            sde2[t] += sde2[t + s];
            sdh[t]  += sdh[t + s];
            sdh2[t] += sdh2[t + s];
        }
        __syncthreads();
    }
    if (t == 0) {
        float mu  = (float)(sde[0] / (double)NE);
        float var = (float)(sde2[0] / (double)NE) - mu * mu;
        float rs = gamma_e[ch] * rsqrtf(var + 1e-5f);
        g_rs_e[ch] = rs;
        g_ofs_e[ch] = beta_e[ch] - mu * rs;

        float muh  = (float)(sdh[0] / (double)BV);
        float varh = (float)(sdh2[0] / (double)BV) - muh * muh;
        float rsh = gamma_h[ch] * rsqrtf(varh + 1e-5f);
        g_rs_h[ch] = rsh;
        g_ofs_h[ch] = beta_h[ch] - muh * rsh;
    }
}

// ------------------------- K3: fused finish (e / h / x) -------------------
__global__ void __launch_bounds__(256)
k_finish(const float* __restrict__ e, float* __restrict__ oe,
         const float* __restrict__ h, float* __restrict__ out_h,
         const float* __restrict__ x, const float* __restrict__ cp,
         const float* __restrict__ ebp, float* __restrict__ out_x) {
    int bx = blockIdx.x;
    if (bx < 8192) {
        int tid = threadIdx.x;
        int base = bx * 1024 + tid;
        int c4 = tid & 31;
        float4 rs = *(const float4*)(g_rs_e + 4 * c4);
        float4 of = *(const float4*)(g_ofs_e + 4 * c4);
        uint2 hv[4];
        float4 ev[4];
        #pragma unroll
        for (int q = 0; q < 4; q++) {
            hv[q] = __ldcs((const uint2*)g_enew + base + q * 256);  // dead after read
            ev[q] = __ldg((const float4*)e + base + q * 256);       // keep e in L2
        }
        #pragma unroll
        for (int q = 0; q < 4; q++) {
            float2 e01 = __half22float2(*reinterpret_cast<__half2*>(&hv[q].x));
            float2 e23 = __half22float2(*reinterpret_cast<__half2*>(&hv[q].y));
            float4 r = ev[q];
            r.x += fmaxf(fmaf(e01.x, rs.x, of.x), 0.f);
            r.y += fmaxf(fmaf(e01.y, rs.y, of.y), 0.f);
            r.z += fmaxf(fmaf(e23.x, rs.z, of.z), 0.f);
            r.w += fmaxf(fmaf(e23.y, rs.w, of.w), 0.f);
            __stcs((float4*)oe + base + q * 256, r);                // never re-read
        }
    } else if (bx < 8192 + 512) {
        int idx = (bx - 8192) * 256 + threadIdx.x;
        int ch = idx & 127;
        float v = fmaf(g_hpre[idx], g_rs_h[ch], g_ofs_h[ch]);
        out_h[idx] = h[idx] + fmaxf(v, 0.f);
    } else {
        __shared__ float rx[8], ry[8];
        int i = bx - 8192 - 512;      // node 0..1023
        int j = threadIdx.x;
        int lane = j & 31, wd = j >> 5;
        int b = i >> 8;
        float xi = x[i * 2], yi = x[i * 2 + 1];
        float pd = g_pd0[(size_t)i * Vn + j] + g_pd1[(size_t)i * Vn + j];
        float pa = sigmoidf_(pd + ebp[0]);
        float dx = xi - x[(b * Vn + j) * 2];
        float dy = yi - x[(b * Vn + j) * 2 + 1];
        float px = pa * dx, py = pa * dy;
        #pragma unroll
        for (int o = 16; o > 0; o >>= 1) {
            px += __shfl_xor_sync(0xffffffffu, px, o);
            py += __shfl_xor_sync(0xffffffffu, py, o);
        }
        if (lane == 0) { rx[wd] = px; ry[wd] = py; }
        __syncthreads();
        if (j == 0) {
            float sx = 0.f, sy = 0.f;
            #pragma unroll
            for (int w = 0; w < 8; w++) { sx += rx[w]; sy += ry[w]; }
            float c = cp[0];
            out_x[i * 2]     = xi + c * sx;
            out_x[i * 2 + 1] = yi + c * sy;
        }
    }
}

// ------------------------- launcher ---------------------------------------
extern "C" void kernel_launch(void* const* d_in, const int* in_sizes, int n_in,
                              void* d_out, int out_size) {
    const float* h     = (const float*)d_in[0];
    const float* e     = (const float*)d_in[1];
    const float* x     = (const float*)d_in[2];
    const int*   graph = (const int*)d_in[3];
    const float* Uw = (const float*)d_in[4],  *Ub = (const float*)d_in[5];
    const float* Vw = (const float*)d_in[6],  *Vb = (const float*)d_in[7];
    const float* Aw = (const float*)d_in[8],  *Ab = (const float*)d_in[9];
    const float* Bw = (const float*)d_in[10], *Bb = (const float*)d_in[11];
    const float* Cw = (const float*)d_in[12], *Cb = (const float*)d_in[13];
    const float* dwv = (const float*)d_in[14], *dbv = (const float*)d_in[15];
    const float* ewv = (const float*)d_in[16], *ebp = (const float*)d_in[17];
    const float* cp  = (const float*)d_in[18];
    const float* gh  = (const float*)d_in[19], *bh = (const float*)d_in[20];
    const float* ge  = (const float*)d_in[21], *be = (const float*)d_in[22];

    float* out_h = (float*)d_out;
    float* out_e = out_h + (size_t)BV * Hn;
    float* out_x = out_e + (size_t)NE * Hn;

    cudaFuncSetAttribute(k_main, cudaFuncAttributeMaxDynamicSharedMemorySize, SMEM_MAIN);

    k_pre<<<272, 256>>>(h, Cw, Uw, Ub, Vw, Vb, Aw, Ab, Bw, Bb);
    k_main<<<4096, 256, SMEM_MAIN>>>(e, x, graph, Cb, dwv, dbv, ewv);
    k_stats1<<<1024, 128>>>();
    k_stats2<<<128, 256>>>(gh, bh, ge, be);
    k_finish<<<8192 + 512 + BV, 256>>>(e, out_e, h, out_h, x, cp, ebp, out_x);
}

// round 15
// speedup vs baseline: 2.0389x; 1.0117x over previous
#include <cuda_runtime.h>
#include <cuda_fp16.h>
#include <cstdint>

// Problem constants
#define Hn 128
#define Vn 256
#define BV 1024            // B*V node count
#define NE 262144          // B*V*V edge count

// ------------------------- device scratch --------------------------------
__device__ float g_Uh[BV * Hn];
__device__ float g_Vh[BV * Hn];
__device__ float g_Ah[BV * Hn];
__device__ float g_Bh[BV * Hn];
__device__ float g_hpre[BV * Hn];
__device__ float g_hpp[2048 * Hn];     // per-(i,jh) masked-aggregation partial
__device__ float g_ps[2048 * Hn];      // per-(i,jh) per-channel sum of e_new
__device__ float g_ps2[2048 * Hn];
__device__ float g_pd0[NE];            // pa-dot partial, n-half 0
__device__ float g_pd1[NE];            // pa-dot partial, n-half 1
__device__ float g_rs_e[Hn], g_ofs_e[Hn];
__device__ float g_rs_h[Hn], g_ofs_h[Hn];
__device__ uint8_t g_CwHi[32768];      // pre-swizzled fp16 Cw
__device__ __half g_enew[(size_t)NE * Hn];   // e_new in fp16 (64 MB)

__device__ __forceinline__ float sigmoidf_(float v) {
    return 1.0f / (1.0f + __expf(-v));
}

__device__ __forceinline__ uint32_t smem_u32(const void* p) {
    uint32_t a;
    asm("{ .reg .u64 t; cvta.to.shared.u64 t, %1; cvt.u32.u64 %0, t; }"
        : "=r"(a) : "l"(p));
    return a;
}

__device__ __forceinline__ uint32_t h2u(__half2 h) {
    return *reinterpret_cast<uint32_t*>(&h);
}

__device__ __forceinline__ __half2 u2h(uint32_t u) {
    return *reinterpret_cast<__half2*>(&u);
}

__device__ __forceinline__ void ldsm_x4(uint32_t& r0, uint32_t& r1, uint32_t& r2,
                                        uint32_t& r3, uint32_t addr) {
    asm volatile("ldmatrix.sync.aligned.m8n8.x4.shared.b16 {%0,%1,%2,%3}, [%4];"
                 : "=r"(r0), "=r"(r1), "=r"(r2), "=r"(r3) : "r"(addr));
}

__device__ __forceinline__ void mma16816(float* d, const uint32_t* a, const uint32_t* b) {
    asm volatile(
        "mma.sync.aligned.m16n8k16.row.col.f32.f16.f16.f32 "
        "{%0,%1,%2,%3}, {%4,%5,%6,%7}, {%8,%9}, {%0,%1,%2,%3};"
        : "+f"(d[0]), "+f"(d[1]), "+f"(d[2]), "+f"(d[3])
        : "r"(a[0]), "r"(a[1]), "r"(a[2]), "r"(a[3]), "r"(b[0]), "r"(b[1]));
}

__device__ __forceinline__ int sw_off(int idx /*float4 index*/) {
    int row = idx >> 5;
    int c4f = idx & 31;
    return row * 256 + (((c4f >> 1) ^ (row & 7)) << 4) + ((c4f & 1) << 3);
}

// ------------------------- K0: fused Cw prep + node linears ---------------
// grid 272: blocks 0..15 convert Cw; blocks 16..271 = (matrix, 16-row block)
__global__ void __launch_bounds__(256)
k_pre(const float* __restrict__ h, const float* __restrict__ Cw,
      const float* __restrict__ Uw, const float* __restrict__ Ub,
      const float* __restrict__ Vw, const float* __restrict__ Vb,
      const float* __restrict__ Aw, const float* __restrict__ Ab,
      const float* __restrict__ Bw, const float* __restrict__ Bb) {
    __shared__ float hs[16 * Hn];
    int tid = threadIdx.x;
    int bx = blockIdx.x;
    if (bx < 16) {
        int idx = bx * 256 + tid;     // 4096 float4s
        float4 v = __ldg((const float4*)Cw + idx);
        __half2 h0 = __floats2half2_rn(v.x, v.y);
        __half2 h1 = __floats2half2_rn(v.z, v.w);
        *(uint2*)(g_CwHi + sw_off(idx)) = make_uint2(h2u(h0), h2u(h1));
        return;
    }
    int bx2 = bx - 16;                // 0..255
    int m = bx2 & 3;                  // matrix id
    int row0 = (bx2 >> 2) * 16;       // 16-row block
    for (int idx = tid; idx < 16 * Hn; idx += 256)
        hs[idx] = h[(size_t)row0 * Hn + idx];
    __syncthreads();
    const float* Ws[4] = {Uw, Vw, Aw, Bw};
    const float* bs[4] = {Ub, Vb, Ab, Bb};
    float* outs[4];
    outs[0] = g_Uh; outs[1] = g_Vh; outs[2] = g_Ah; outs[3] = g_Bh;

    int half = tid >> 7;              // 0/1 -> rows [half*8, half*8+8)
    int o = tid & 127;
    const float* W = Ws[m] + (size_t)o * Hn;
    float acc[8];
    #pragma unroll
    for (int r = 0; r < 8; r++) acc[r] = 0.f;
    const float* hrow = hs + half * 8 * Hn;
    for (int k = 0; k < Hn; k += 4) {
        float4 w = *(const float4*)(W + k);
        #pragma unroll
        for (int r = 0; r < 8; r++) {
            acc[r] += hrow[r * Hn + k] * w.x + hrow[r * Hn + k + 1] * w.y +
                      hrow[r * Hn + k + 2] * w.z + hrow[r * Hn + k + 3] * w.w;
        }
    }
    float bias = bs[m][o];
    float* op = outs[m] + (size_t)(row0 + half * 8) * Hn + o;
    #pragma unroll
    for (int r = 0; r < 8; r++) op[(size_t)r * Hn] = acc[r] + bias;
}

// ------------------------- K1: main kernel (128j x 64n tile, fp16) --------
// grid 4096: blockIdx = ((i_glob*2 + jh)*2 + nh)
static constexpr int SA      = 0;      // 32768
static constexpr int SB      = 32768;  // 16384 -> 49152
// post-MMA aliases:
static constexpr int SM_STG  = 0;      // 128 x 32 uint32 (fp16 stage) = 16384
static constexpr int SM_PD   = 16384;  // 128 x 17 f = 8704 (inside SA)
static constexpr int SM_RPS  = 32768;  // 16x64 f -> 36864
static constexpr int SM_RPS2 = 36864;  // -> 40960
static constexpr int SM_RM   = 40960;  // -> 45056 (inside SB)
// persistent misc:
static constexpr int SM_BC   = 49152;  // 128 f
static constexpr int SM_DW   = 49664;
static constexpr int SM_EW   = 50176;
static constexpr int SM_DIST = 50688;
static constexpr int SM_GR   = 51200;  // -> 51712
static constexpr int SMEM_MAIN = 51712;

__global__ void __launch_bounds__(256, 4)
k_main(const float* __restrict__ e, const float* __restrict__ x,
       const int* __restrict__ graph, const float* __restrict__ Cb,
       const float* __restrict__ dwv, const float* __restrict__ dbv,
       const float* __restrict__ ewv) {
    extern __shared__ char sm[];
    uint32_t smb = smem_u32(sm);
    int tid = threadIdx.x;
    int wid = tid >> 5;
    int lane = tid & 31;

    int bx = blockIdx.x;
    int i_glob = bx >> 2;          // b*V + i
    int jh = (bx >> 1) & 1;
    int nh = bx & 1;
    int b = i_glob >> 8;
    int jbase = jh * 128;

    float* sBC   = (float*)(sm + SM_BC);
    float* sdw   = (float*)(sm + SM_DW);
    float* sew   = (float*)(sm + SM_EW);
    float* sdist = (float*)(sm + SM_DIST);
    int*   sgr   = (int*)(sm + SM_GR);
    float* spd   = (float*)(sm + SM_PD);
    float* rps   = (float*)(sm + SM_RPS);
    float* rps2  = (float*)(sm + SM_RPS2);
    float* rmm   = (float*)(sm + SM_RM);

    float xi = x[i_glob * 2], yi = x[i_glob * 2 + 1];
    if (tid < 128) {
        sBC[tid] = g_Bh[(size_t)i_glob * Hn + tid] + Cb[tid] + dbv[tid];
        sdw[tid] = dwv[tid];
        sew[tid] = ewv[tid];
        int jg = jbase + tid;
        float dx = xi - x[(b * Vn + jg) * 2];
        float dy = yi - x[(b * Vn + jg) * 2 + 1];
        float d2 = dx * dx + dy * dy;
        sdist[tid] = d2 > 0.f ? sqrtf(d2) : 0.f;
        sgr[tid] = graph[(size_t)i_glob * Vn + jg];
    }

    // A: load + convert e tile (128x128) to fp16
    {
        const float4* src = (const float4*)(e + ((size_t)i_glob * Vn + jbase) * Hn);
        #pragma unroll
        for (int q = 0; q < 16; q++) {
            int idx = tid + 256 * q;
            float4 v = __ldg(src + idx);
            __half2 h0 = __floats2half2_rn(v.x, v.y);
            __half2 h1 = __floats2half2_rn(v.z, v.w);
            *(uint2*)(sm + SA + sw_off(idx)) = make_uint2(h2u(h0), h2u(h1));
        }
    }
    // B: straight copy of pre-converted Cw rows [nh*64, nh*64+64)
    {
        const uint4* srcH = (const uint4*)(g_CwHi) + nh * 1024;
        uint4* dstH = (uint4*)(sm + SB);
        #pragma unroll
        for (int t = tid; t < 1024; t += 256)
            dstH[t] = __ldg(srcH + t);
    }
    __syncthreads();

    // ---- MMA: warp grid 4(m) x 2(n); warp tile 32x32 ----
    int wm = wid & 3;
    int wn = wid >> 2;

    float acc[2][4][4];
    #pragma unroll
    for (int mi = 0; mi < 2; mi++)
        #pragma unroll
        for (int ni = 0; ni < 4; ni++)
            #pragma unroll
            for (int c = 0; c < 4; c++) acc[mi][ni][c] = 0.f;

    int la7 = lane & 7;
    int rowA_base = wm * 32 + la7 + ((lane >> 3) & 1) * 8;
    int a_ch = lane >> 4;
    int b_tile = lane >> 3;
    int b_nip = b_tile >> 1;
    int b_ch = b_tile & 1;
    int rowB_lane = wn * 32 + la7;

    #pragma unroll
    for (int ks = 0; ks < 8; ks++) {
        uint32_t ah[2][4];
        #pragma unroll
        for (int mi = 0; mi < 2; mi++) {
            int r = rowA_base + mi * 16;
            uint32_t off = r * 256 + (((ks * 2 + a_ch) ^ (r & 7)) << 4);
            ldsm_x4(ah[mi][0], ah[mi][1], ah[mi][2], ah[mi][3], smb + SA + off);
        }
        uint32_t bh[4][2];
        #pragma unroll
        for (int p = 0; p < 2; p++) {
            int r = rowB_lane + (p * 2 + b_nip) * 8;
            uint32_t off = r * 256 + (((ks * 2 + b_ch) ^ (r & 7)) << 4);
            ldsm_x4(bh[p * 2][0], bh[p * 2][1], bh[p * 2 + 1][0], bh[p * 2 + 1][1],
                    smb + SB + off);
        }
        #pragma unroll
        for (int mi = 0; mi < 2; mi++)
            #pragma unroll
            for (int ni = 0; ni < 4; ni++)
                mma16816(acc[mi][ni], ah[mi], bh[ni]);
    }
    __syncthreads();   // MMA done: SA -> stage+pd, SB -> reductions

    // ---- stage accumulators as fp16 into SM_STG (128 rows x 32 half2) ----
    uint32_t* stage16 = (uint32_t*)(sm + SM_STG);
    {
        #pragma unroll
        for (int mi = 0; mi < 2; mi++) {
            #pragma unroll
            for (int rh = 0; rh < 2; rh++) {
                int r = wm * 32 + mi * 16 + (lane >> 2) + rh * 8;
                int sx = (r & 7) << 2;
                #pragma unroll
                for (int ni = 0; ni < 4; ni++) {
                    int hc = wn * 16 + ni * 4 + (lane & 3);
                    __half2 hp = __floats2half2_rn(acc[mi][ni][rh * 2],
                                                   acc[mi][ni][rh * 2 + 1]);
                    stage16[r * 32 + (hc ^ sx)] = h2u(hp);
                }
            }
        }
    }
    __syncthreads();

    // ---- coalesced epilogue: thread = (row-group rg, col-group cg4) ----
    int cg4 = tid & 15;
    int rg  = tid >> 4;
    int cgl = cg4 * 4;
    int cgg = nh * 64 + cgl;
    float4 bc4 = *(const float4*)(sBC + cgg);
    float4 dw4 = *(const float4*)(sdw + cgg);
    float4 ew4 = *(const float4*)(sew + cgg);
    float4 cs  = make_float4(0.f, 0.f, 0.f, 0.f);
    float4 cq  = make_float4(0.f, 0.f, 0.f, 0.f);
    float4 cm  = make_float4(0.f, 0.f, 0.f, 0.f);

    __half* eh = g_enew + ((size_t)i_glob * Vn + jbase) * Hn;

    #pragma unroll
    for (int k = 0; k < 8; k++) {
        int r = rg + 16 * k;
        int hc2 = (cg4 * 2) ^ ((r & 7) << 2);
        uint2 sv = *(const uint2*)(stage16 + r * 32 + hc2);
        float2 f01 = __half22float2(u2h(sv.x));
        float2 f23 = __half22float2(u2h(sv.y));
        size_t nrow = ((size_t)(b * Vn + jbase + r)) * Hn + cgg;
        float4 a  = __ldg((const float4*)(g_Ah + nrow));
        float4 vh = __ldg((const float4*)(g_Vh + nrow));
        float dist = sdist[r];
        bool keep = (sgr[r] != 1);
        float t0 = f01.x + a.x + bc4.x + dist * dw4.x;
        float t1 = f01.y + a.y + bc4.y + dist * dw4.y;
        float t2 = f23.x + a.z + bc4.z + dist * dw4.z;
        float t3 = f23.y + a.w + bc4.w + dist * dw4.w;
        __half2 p0 = __floats2half2_rn(t0, t1);
        __half2 p1 = __floats2half2_rn(t2, t3);
        *(uint2*)(eh + (size_t)r * Hn + cgg) = make_uint2(h2u(p0), h2u(p1));
        cs.x += t0; cs.y += t1; cs.z += t2; cs.w += t3;
        cq.x += t0 * t0; cq.y += t1 * t1; cq.z += t2 * t2; cq.w += t3 * t3;
        if (keep) {
            cm.x += sigmoidf_(t0) * vh.x;
            cm.y += sigmoidf_(t1) * vh.y;
            cm.z += sigmoidf_(t2) * vh.z;
            cm.w += sigmoidf_(t3) * vh.w;
        }
        spd[r * 17 + cg4] = t0 * ew4.x + t1 * ew4.y + t2 * ew4.z + t3 * ew4.w;
    }

    *(float4*)(rps  + rg * 64 + cgl) = cs;
    *(float4*)(rps2 + rg * 64 + cgl) = cq;
    *(float4*)(rmm  + rg * 64 + cgl) = cm;
    __syncthreads();

    if (tid < 64) {
        float s = 0.f, s2 = 0.f, mm = 0.f;
        #pragma unroll
        for (int g = 0; g < 16; g++) {
            s  += rps[g * 64 + tid];
            s2 += rps2[g * 64 + tid];
            mm += rmm[g * 64 + tid];
        }
        size_t gi = ((size_t)i_glob * 2 + jh) * Hn + nh * 64 + tid;
        g_ps[gi]  = s;
        g_ps2[gi] = s2;
        g_hpp[gi] = mm;
    }
    if (tid >= 128) {
        int r = tid - 128;
        float pdt = 0.f;
        #pragma unroll
        for (int q = 0; q < 16; q++) pdt += spd[r * 17 + q];
        float* gpd = nh ? g_pd1 : g_pd0;
        gpd[(size_t)i_glob * Vn + jbase + r] = pdt;
    }
}

// ------------------------- K2: fused BN statistics (1 block per channel) --
__global__ void __launch_bounds__(256)
k_stats(const float* __restrict__ gamma_h, const float* __restrict__ beta_h,
        const float* __restrict__ gamma_e, const float* __restrict__ beta_e) {
    __shared__ double sde[256], sde2[256], sdh[256], sdh2[256];
    int ch = blockIdx.x;       // 128 blocks, one per channel
    int t = threadIdx.x;

    // e-sums: fold 8 raw (i,jh) partials per thread (2048 total)
    double se = 0.0, se2 = 0.0;
    #pragma unroll
    for (int q = 0; q < 8; q++) {
        int p = t + q * 256;
        se  += (double)g_ps[(size_t)p * Hn + ch];
        se2 += (double)g_ps2[(size_t)p * Hn + ch];
    }
    // h: 4 nodes per thread; compute hpre inline
    double sh = 0.0, sh2 = 0.0;
    #pragma unroll
    for (int q = 0; q < 4; q++) {
        int i = t + q * 256;
        float hv = g_Uh[(size_t)i * Hn + ch] +
                   g_hpp[(size_t)(2 * i) * Hn + ch] +
                   g_hpp[(size_t)(2 * i + 1) * Hn + ch];
        g_hpre[(size_t)i * Hn + ch] = hv;
        sh += (double)hv;
        sh2 += (double)hv * (double)hv;
    }
    sde[t] = se; sde2[t] = se2; sdh[t] = sh; sdh2[t] = sh2;
    __syncthreads();
    #pragma unroll
    for (int s = 128; s > 0; s >>= 1) {
        if (t < s) {
            sde[t]  += sde[t + s];
            sde2[t] += sde2[t + s];
            sdh[t]  += sdh[t + s];
            sdh2[t] += sdh2[t + s];
        }
        __syncthreads();
    }
    if (t == 0) {
        float mu  = (float)(sde[0] / (double)NE);
        float var = (float)(sde2[0] / (double)NE) - mu * mu;
        float rs = gamma_e[ch] * rsqrtf(var + 1e-5f);
        g_rs_e[ch] = rs;
        g_ofs_e[ch] = beta_e[ch] - mu * rs;

        float muh  = (float)(sdh[0] / (double)BV);
        float varh = (float)(sdh2[0] / (double)BV) - muh * muh;
        float rsh = gamma_h[ch] * rsqrtf(varh + 1e-5f);
        g_rs_h[ch] = rsh;
        g_ofs_h[ch] = beta_h[ch] - muh * rsh;
    }
}

// ------------------------- K3: fused finish (e / h / x) -------------------
__global__ void __launch_bounds__(256)
k_finish(const float* __restrict__ e, float* __restrict__ oe,
         const float* __restrict__ h, float* __restrict__ out_h,
         const float* __restrict__ x, const float* __restrict__ cp,
         const float* __restrict__ ebp, float* __restrict__ out_x) {
    int bx = blockIdx.x;
    if (bx < 8192) {
        int tid = threadIdx.x;
        int base = bx * 1024 + tid;
        int c4 = tid & 31;
        float4 rs = *(const float4*)(g_rs_e + 4 * c4);
        float4 of = *(const float4*)(g_ofs_e + 4 * c4);
        uint2 hv[4];
        float4 ev[4];
        #pragma unroll
        for (int q = 0; q < 4; q++) {
            hv[q] = __ldcs((const uint2*)g_enew + base + q * 256);  // dead after read
            ev[q] = __ldg((const float4*)e + base + q * 256);       // keep e in L2
        }
        #pragma unroll
        for (int q = 0; q < 4; q++) {
            float2 e01 = __half22float2(*reinterpret_cast<__half2*>(&hv[q].x));
            float2 e23 = __half22float2(*reinterpret_cast<__half2*>(&hv[q].y));
            float4 r = ev[q];
            r.x += fmaxf(fmaf(e01.x, rs.x, of.x), 0.f);
            r.y += fmaxf(fmaf(e01.y, rs.y, of.y), 0.f);
            r.z += fmaxf(fmaf(e23.x, rs.z, of.z), 0.f);
            r.w += fmaxf(fmaf(e23.y, rs.w, of.w), 0.f);
            __stcs((float4*)oe + base + q * 256, r);                // never re-read
        }
    } else if (bx < 8192 + 512) {
        int idx = (bx - 8192) * 256 + threadIdx.x;
        int ch = idx & 127;
        float v = fmaf(g_hpre[idx], g_rs_h[ch], g_ofs_h[ch]);
        out_h[idx] = h[idx] + fmaxf(v, 0.f);
    } else {
        __shared__ float rx[8], ry[8];
        int i = bx - 8192 - 512;      // node 0..1023
        int j = threadIdx.x;
        int lane = j & 31, wd = j >> 5;
        int b = i >> 8;
        float xi = x[i * 2], yi = x[i * 2 + 1];
        float pd = g_pd0[(size_t)i * Vn + j] + g_pd1[(size_t)i * Vn + j];
        float pa = sigmoidf_(pd + ebp[0]);
        float dx = xi - x[(b * Vn + j) * 2];
        float dy = yi - x[(b * Vn + j) * 2 + 1];
        float px = pa * dx, py = pa * dy;
        #pragma unroll
        for (int o = 16; o > 0; o >>= 1) {
            px += __shfl_xor_sync(0xffffffffu, px, o);
            py += __shfl_xor_sync(0xffffffffu, py, o);
        }
        if (lane == 0) { rx[wd] = px; ry[wd] = py; }
        __syncthreads();
        if (j == 0) {
            float sx = 0.f, sy = 0.f;
            #pragma unroll
            for (int w = 0; w < 8; w++) { sx += rx[w]; sy += ry[w]; }
            float c = cp[0];
            out_x[i * 2]     = xi + c * sx;
            out_x[i * 2 + 1] = yi + c * sy;
        }
    }
}

// ------------------------- launcher ---------------------------------------
extern "C" void kernel_launch(void* const* d_in, const int* in_sizes, int n_in,
                              void* d_out, int out_size) {
    const float* h     = (const float*)d_in[0];
    const float* e     = (const float*)d_in[1];
    const float* x     = (const float*)d_in[2];
    const int*   graph = (const int*)d_in[3];
    const float* Uw = (const float*)d_in[4],  *Ub = (const float*)d_in[5];
    const float* Vw = (const float*)d_in[6],  *Vb = (const float*)d_in[7];
    const float* Aw = (const float*)d_in[8],  *Ab = (const float*)d_in[9];
    const float* Bw = (const float*)d_in[10], *Bb = (const float*)d_in[11];
    const float* Cw = (const float*)d_in[12], *Cb = (const float*)d_in[13];
    const float* dwv = (const float*)d_in[14], *dbv = (const float*)d_in[15];
    const float* ewv = (const float*)d_in[16], *ebp = (const float*)d_in[17];
    const float* cp  = (const float*)d_in[18];
    const float* gh  = (const float*)d_in[19], *bh = (const float*)d_in[20];
    const float* ge  = (const float*)d_in[21], *be = (const float*)d_in[22];

    float* out_h = (float*)d_out;
    float* out_e = out_h + (size_t)BV * Hn;
    float* out_x = out_e + (size_t)NE * Hn;

    cudaFuncSetAttribute(k_main, cudaFuncAttributeMaxDynamicSharedMemorySize, SMEM_MAIN);

    k_pre<<<272, 256>>>(h, Cw, Uw, Ub, Vw, Vb, Aw, Ab, Bw, Bb);
    k_main<<<4096, 256, SMEM_MAIN>>>(e, x, graph, Cb, dwv, dbv, ewv);
    k_stats<<<128, 256>>>(gh, bh, ge, be);
    k_finish<<<8192 + 512 + BV, 256>>>(e, out_e, h, out_h, x, cp, ebp, out_x);
}